// round 6
// baseline (speedup 1.0000x reference)
#include <cuda_runtime.h>
#include <cuda_bf16.h>
#include <cstdint>
#include <math.h>

// Problem constants
#define B_    2
#define L_    2048
#define E_    1024
#define H_    16
#define HD_   64
#define KD_   1024
#define NQKV_ 3072
#define ML_   (B_*L_)   // 4096

// ---------------- GEMM tiling ----------------
#define BM 128
#define BN 128
#define BK 64
#define GEMM_THREADS 256
#define ROWB 144                    // 128B data + 16B pad (conflict-free ldsm)
#define LO_OFF  (128 * ROWB)
#define B_OFF   (256 * ROWB)
#define STAGEB  (512 * ROWB)        // 73728
#define NSTAGE 2
#define GEMM_SMEM (NSTAGE * STAGEB) // 147456

// ---------------- attention tiling ----------------
#define AROWB 144
#define S_QH 0
#define S_QL (S_QH + 64*AROWB)
#define S_KH (S_QL + 64*AROWB)
#define S_KL (S_KH + 128*AROWB)
#define S_VH (S_KL + 128*AROWB)
#define S_VL (S_VH + 128*AROWB)
#define S_OK (S_VL + 128*AROWB)
#define ATTN_SMEM (S_OK + 128*4)

// ---------------- scratch ----------------
__device__ __nv_bfloat16 g_qkvh[(size_t)ML_ * NQKV_];
__device__ __nv_bfloat16 g_qkvl[(size_t)ML_ * NQKV_];
__device__ __nv_bfloat16 g_xh[(size_t)ML_ * KD_];
__device__ __nv_bfloat16 g_xl[(size_t)ML_ * KD_];
__device__ __nv_bfloat16 g_oh[(size_t)ML_ * E_];
__device__ __nv_bfloat16 g_ol[(size_t)ML_ * E_];
__device__ __nv_bfloat16 g_wqh[(size_t)NQKV_ * KD_];
__device__ __nv_bfloat16 g_wql[(size_t)NQKV_ * KD_];
__device__ __nv_bfloat16 g_woh[(size_t)E_ * E_];
__device__ __nv_bfloat16 g_wol[(size_t)E_ * E_];

// ---------------- helpers ----------------
__device__ __forceinline__ uint32_t smem_u32(const void* p) {
    uint32_t a;
    asm("{ .reg .u64 t; cvta.to.shared.u64 t, %1; cvt.u32.u64 %0, t; }" : "=r"(a) : "l"(p));
    return a;
}
#define CP16(dst, src) \
    asm volatile("cp.async.cg.shared.global [%0], [%1], 16;" :: "r"(dst), "l"(src))
#define CP_COMMIT() asm volatile("cp.async.commit_group;" ::: "memory")
#define CP_WAIT(n)  asm volatile("cp.async.wait_group %0;" :: "n"(n) : "memory")

#define LDSM_X4(r0, r1, r2, r3, a) \
    asm volatile("ldmatrix.sync.aligned.m8n8.x4.shared.b16 {%0,%1,%2,%3}, [%4];" \
                 : "=r"(r0), "=r"(r1), "=r"(r2), "=r"(r3) : "r"(a))
#define LDSM_X4_T(r0, r1, r2, r3, a) \
    asm volatile("ldmatrix.sync.aligned.m8n8.x4.trans.shared.b16 {%0,%1,%2,%3}, [%4];" \
                 : "=r"(r0), "=r"(r1), "=r"(r2), "=r"(r3) : "r"(a))

__device__ __forceinline__ void mma_bf16(float c[4], const uint32_t a[4],
                                         uint32_t b0, uint32_t b1) {
    asm volatile(
        "mma.sync.aligned.m16n8k16.row.col.f32.bf16.bf16.f32 "
        "{%0,%1,%2,%3}, {%4,%5,%6,%7}, {%8,%9}, {%0,%1,%2,%3};"
        : "+f"(c[0]), "+f"(c[1]), "+f"(c[2]), "+f"(c[3])
        : "r"(a[0]), "r"(a[1]), "r"(a[2]), "r"(a[3]), "r"(b0), "r"(b1));
}

__device__ __forceinline__ void hilo2(float x, float y, uint32_t& hi, uint32_t& lo) {
    __nv_bfloat16 hx = __float2bfloat16(x), hy = __float2bfloat16(y);
    __nv_bfloat162 h2 = __halves2bfloat162(hx, hy);
    __nv_bfloat162 l2 = __halves2bfloat162(__float2bfloat16(x - __bfloat162float(hx)),
                                           __float2bfloat16(y - __bfloat162float(hy)));
    hi = *(uint32_t*)&h2;
    lo = *(uint32_t*)&l2;
}

// ---------------------------------------------------------------------------
// C[M,N] = Ah*Bh^T + Ah*Bl^T + Al*Bh^T + bias
// 256 threads, 4x2 warp grid, warp tile 32x64, BK=64, 2-stage cp.async,
// fragment double-buffer across k16 steps, product-major MMA order.
// ---------------------------------------------------------------------------
template<bool HILO>
__global__ __launch_bounds__(GEMM_THREADS, 1)
void gemm_mma(const __nv_bfloat16* __restrict__ Ah, const __nv_bfloat16* __restrict__ Al,
              const __nv_bfloat16* __restrict__ Bh, const __nv_bfloat16* __restrict__ Bl,
              const float* __restrict__ bias, float* __restrict__ Cf,
              uint32_t* __restrict__ Ch, uint32_t* __restrict__ Cl,
              int M, int N, int K)
{
    extern __shared__ char smem[];
    const uint32_t sbase = smem_u32(smem);
    const int tid  = threadIdx.x;
    const int lane = tid & 31;
    const int wid  = tid >> 5;
    const int warp_m = wid >> 1;     // 0..3 -> rows warp_m*32
    const int warp_n = wid & 1;      // 0..1 -> cols warp_n*64
    const int bm = blockIdx.y * BM;
    const int bn = blockIdx.x * BN;
    const int NT = K / BK;

    // ---- loader: 16 chunks of 16B per stage, pointers recomputed ----
    const int lrow = tid >> 3;          // 0..31
    const int lc   = tid & 7;           // 16B chunk in 128B row
    const __nv_bfloat16* base0 = Ah + (size_t)(bm + lrow) * K + lc * 8;
    const __nv_bfloat16* base1 = Al + (size_t)(bm + lrow) * K + lc * 8;
    const __nv_bfloat16* base2 = Bh + (size_t)(bn + lrow) * K + lc * 8;
    const __nv_bfloat16* base3 = Bl + (size_t)(bn + lrow) * K + lc * 8;
    const uint32_t dbase = (uint32_t)(lrow * ROWB + lc * 16);
    const size_t rstep = (size_t)32 * K;

    auto stage_load = [&](int stage, int kt) {
        uint32_t sb = sbase + stage * STAGEB + dbase;
        size_t koff = (size_t)kt * BK;
#pragma unroll
        for (int j = 0; j < 4; ++j) {
            CP16(sb + j * (32 * ROWB),                     base0 + j * rstep + koff);
            CP16(sb + j * (32 * ROWB) + LO_OFF,            base1 + j * rstep + koff);
            CP16(sb + j * (32 * ROWB) + B_OFF,             base2 + j * rstep + koff);
            CP16(sb + j * (32 * ROWB) + B_OFF + LO_OFF,    base3 + j * rstep + koff);
        }
    };

    const uint32_t aOff = (uint32_t)((warp_m * 32 + (lane & 15)) * ROWB + (lane >> 4) * 16);
    const uint32_t bOff = (uint32_t)(B_OFF +
        (warp_n * 64 + ((lane >> 4) << 3) + (lane & 7)) * ROWB + ((lane >> 3) & 1) * 16);

    float acc[2][8][4];
#pragma unroll
    for (int mt = 0; mt < 2; ++mt)
#pragma unroll
        for (int nt = 0; nt < 8; ++nt)
#pragma unroll
            for (int j = 0; j < 4; ++j) acc[mt][nt][j] = 0.0f;

    // fragment double buffers
    uint32_t ah[2][2][4], al[2][2][4], bh[2][8][2], bl[2][8][2];

    stage_load(0, 0); CP_COMMIT();

    for (int kt = 0; kt < NT; ++kt) {
        CP_WAIT(0);
        __syncthreads();
        if (kt + 1 < NT) { stage_load((kt + 1) & 1, kt + 1); CP_COMMIT(); }

        const uint32_t st = sbase + (kt & 1) * STAGEB;

        // load frags for s=0 into buffer 0
#pragma unroll
        for (int mt = 0; mt < 2; ++mt) {
            uint32_t a = st + aOff + mt * 16 * ROWB;
            LDSM_X4(ah[0][mt][0], ah[0][mt][1], ah[0][mt][2], ah[0][mt][3], a);
            LDSM_X4(al[0][mt][0], al[0][mt][1], al[0][mt][2], al[0][mt][3], a + LO_OFF);
        }
#pragma unroll
        for (int p = 0; p < 4; ++p) {
            uint32_t a = st + bOff + p * 16 * ROWB;
            LDSM_X4(bh[0][2*p][0], bh[0][2*p][1], bh[0][2*p+1][0], bh[0][2*p+1][1], a);
            LDSM_X4(bl[0][2*p][0], bl[0][2*p][1], bl[0][2*p+1][0], bl[0][2*p+1][1], a + LO_OFF);
        }

#pragma unroll
        for (int s = 0; s < 4; ++s) {
            const int cur = s & 1, nxt = cur ^ 1;
            if (s < 3) {
#pragma unroll
                for (int mt = 0; mt < 2; ++mt) {
                    uint32_t a = st + aOff + mt * 16 * ROWB + (s + 1) * 32;
                    LDSM_X4(ah[nxt][mt][0], ah[nxt][mt][1], ah[nxt][mt][2], ah[nxt][mt][3], a);
                    LDSM_X4(al[nxt][mt][0], al[nxt][mt][1], al[nxt][mt][2], al[nxt][mt][3], a + LO_OFF);
                }
#pragma unroll
                for (int p = 0; p < 4; ++p) {
                    uint32_t a = st + bOff + p * 16 * ROWB + (s + 1) * 32;
                    LDSM_X4(bh[nxt][2*p][0], bh[nxt][2*p][1], bh[nxt][2*p+1][0], bh[nxt][2*p+1][1], a);
                    LDSM_X4(bl[nxt][2*p][0], bl[nxt][2*p][1], bl[nxt][2*p+1][0], bl[nxt][2*p+1][1], a + LO_OFF);
                }
            }
            // product-major MMA: 16 independent HMMAs per group
#pragma unroll
            for (int mt = 0; mt < 2; ++mt)
#pragma unroll
                for (int nt = 0; nt < 8; ++nt)
                    mma_bf16(acc[mt][nt], ah[cur][mt], bh[cur][nt][0], bh[cur][nt][1]);
#pragma unroll
            for (int mt = 0; mt < 2; ++mt)
#pragma unroll
                for (int nt = 0; nt < 8; ++nt)
                    mma_bf16(acc[mt][nt], ah[cur][mt], bl[cur][nt][0], bl[cur][nt][1]);
#pragma unroll
            for (int mt = 0; mt < 2; ++mt)
#pragma unroll
                for (int nt = 0; nt < 8; ++nt)
                    mma_bf16(acc[mt][nt], al[cur][mt], bh[cur][nt][0], bh[cur][nt][1]);
        }
        __syncthreads();
    }

    const int r0 = bm + warp_m * 32 + (lane >> 2);
    const int c0 = bn + warp_n * 64 + (lane & 3) * 2;
#pragma unroll
    for (int mt = 0; mt < 2; ++mt) {
#pragma unroll
        for (int nt = 0; nt < 8; ++nt) {
            int col = c0 + nt * 8;
            float bx = bias[col], by = bias[col + 1];
            float vx0 = acc[mt][nt][0] + bx, vy0 = acc[mt][nt][1] + by;
            float vx1 = acc[mt][nt][2] + bx, vy1 = acc[mt][nt][3] + by;
            int ra = r0 + mt * 16, rb = ra + 8;
            if (HILO) {
                uint32_t h0, l0, h1, l1;
                hilo2(vx0, vy0, h0, l0);
                hilo2(vx1, vy1, h1, l1);
                size_t p0 = (size_t)ra * (N >> 1) + (col >> 1);
                size_t p1 = (size_t)rb * (N >> 1) + (col >> 1);
                Ch[p0] = h0; Cl[p0] = l0;
                Ch[p1] = h1; Cl[p1] = l1;
            } else {
                *(float2*)(Cf + (size_t)ra * N + col) = make_float2(vx0, vy0);
                *(float2*)(Cf + (size_t)rb * N + col) = make_float2(vx1, vy1);
            }
        }
    }
}

// ---------------------------------------------------------------------------
// fp32 -> bf16 hi/lo split
// ---------------------------------------------------------------------------
__global__ __launch_bounds__(256) void split_bf16(
    const float4* __restrict__ src, __nv_bfloat162* __restrict__ hi,
    __nv_bfloat162* __restrict__ lo, int n4)
{
    int i = blockIdx.x * blockDim.x + threadIdx.x;
    if (i >= n4) return;
    float4 v = src[i];
    __nv_bfloat16 h0 = __float2bfloat16(v.x);
    __nv_bfloat16 h1 = __float2bfloat16(v.y);
    __nv_bfloat16 h2 = __float2bfloat16(v.z);
    __nv_bfloat16 h3 = __float2bfloat16(v.w);
    __nv_bfloat16 l0 = __float2bfloat16(v.x - __bfloat162float(h0));
    __nv_bfloat16 l1 = __float2bfloat16(v.y - __bfloat162float(h1));
    __nv_bfloat16 l2 = __float2bfloat16(v.z - __bfloat162float(h2));
    __nv_bfloat16 l3 = __float2bfloat16(v.w - __bfloat162float(h3));
    hi[2 * i]     = __halves2bfloat162(h0, h1);
    hi[2 * i + 1] = __halves2bfloat162(h2, h3);
    lo[2 * i]     = __halves2bfloat162(l0, l1);
    lo[2 * i + 1] = __halves2bfloat162(l2, l3);
}

// ---------------------------------------------------------------------------
// Tensor-core sliding-window attention (unchanged)
// ---------------------------------------------------------------------------
__global__ __launch_bounds__(128, 1) void attn_mma(
    const __nv_bfloat16* __restrict__ qkvh, const __nv_bfloat16* __restrict__ qkvl,
    const int* __restrict__ pmask,
    uint32_t* __restrict__ Oh, uint32_t* __restrict__ Ol)
{
    extern __shared__ char smem[];
    const uint32_t sb = smem_u32(smem);
    const int b = blockIdx.z, h = blockIdx.y, q0 = blockIdx.x * 64;
    const int tid = threadIdx.x, lane = tid & 31, w = tid >> 5;

    for (int i = tid; i < 64 * 8; i += 128) {
        int r = i >> 3, c = i & 7;
        size_t g = (size_t)(b * L_ + q0 + r) * NQKV_ + h * 192 + c * 8;
        *(uint4*)(smem + S_QH + r * AROWB + c * 16) = *(const uint4*)(qkvh + g);
        *(uint4*)(smem + S_QL + r * AROWB + c * 16) = *(const uint4*)(qkvl + g);
    }
    for (int i = tid; i < 128 * 8; i += 128) {
        int r = i >> 3, c = i & 7;
        int pos = q0 - 32 + r;
        uint4 z = make_uint4(0, 0, 0, 0);
        uint4 kh = z, kl = z, vh = z, vl = z;
        if (pos >= 0 && pos < L_) {
            size_t g = (size_t)(b * L_ + pos) * NQKV_ + h * 192 + c * 8;
            kh = *(const uint4*)(qkvh + g + 64);
            kl = *(const uint4*)(qkvl + g + 64);
            vh = *(const uint4*)(qkvh + g + 128);
            vl = *(const uint4*)(qkvl + g + 128);
        }
        *(uint4*)(smem + S_KH + r * AROWB + c * 16) = kh;
        *(uint4*)(smem + S_KL + r * AROWB + c * 16) = kl;
        *(uint4*)(smem + S_VH + r * AROWB + c * 16) = vh;
        *(uint4*)(smem + S_VL + r * AROWB + c * 16) = vl;
    }
    {
        int pos = q0 - 32 + tid;
        int ok = 0;
        if (pos >= 0 && pos < L_) ok = (pmask[b * L_ + pos] != 0);
        ((int*)(smem + S_OK))[tid] = ok;
    }
    __syncthreads();
    const int* okk = (const int*)(smem + S_OK);

    float S[16][4];
#pragma unroll
    for (int i = 0; i < 16; ++i)
#pragma unroll
        for (int j = 0; j < 4; ++j) S[i][j] = 0.0f;

    uint32_t qfh[4][4], qfl[4][4];
    {
        uint32_t aoff = (uint32_t)((w * 16 + (lane & 15)) * AROWB + (lane >> 4) * 16);
#pragma unroll
        for (int ks = 0; ks < 4; ++ks) {
            LDSM_X4(qfh[ks][0], qfh[ks][1], qfh[ks][2], qfh[ks][3], sb + S_QH + aoff + ks * 32);
            LDSM_X4(qfl[ks][0], qfl[ks][1], qfl[ks][2], qfl[ks][3], sb + S_QL + aoff + ks * 32);
        }
    }
    {
        uint32_t boff = (uint32_t)(((((lane >> 4) << 3) + (lane & 7)) * AROWB) + ((lane >> 3) & 1) * 16);
#pragma unroll
        for (int kb = 0; kb < 8; ++kb) {
            uint32_t base = boff + kb * 16 * AROWB;
#pragma unroll
            for (int ks = 0; ks < 4; ++ks) {
                uint32_t bh0, bh1, bh2, bh3, bl0, bl1, bl2, bl3;
                LDSM_X4(bh0, bh1, bh2, bh3, sb + S_KH + base + ks * 32);
                LDSM_X4(bl0, bl1, bl2, bl3, sb + S_KL + base + ks * 32);
                mma_bf16(S[2 * kb],     qfh[ks], bh0, bh1);
                mma_bf16(S[2 * kb],     qfh[ks], bl0, bl1);
                mma_bf16(S[2 * kb],     qfl[ks], bh0, bh1);
                mma_bf16(S[2 * kb + 1], qfh[ks], bh2, bh3);
                mma_bf16(S[2 * kb + 1], qfh[ks], bl2, bl3);
                mma_bf16(S[2 * kb + 1], qfl[ks], bh2, bh3);
            }
        }
    }

    const int rlo = w * 16 + (lane >> 2);
    const int rhi = rlo + 8;
    const float scale = 0.125f;
    const float NEGS = -12500.0f;
    float mlo = -3.0e38f, mhi = -3.0e38f;
#pragma unroll
    for (int nb = 0; nb < 16; ++nb) {
#pragma unroll
        for (int p = 0; p < 2; ++p) {
            int col = nb * 8 + (lane & 3) * 2 + p;
            float s0 = S[nb][p];
            int d0 = col - rlo;
            s0 = (d0 >= 0 && d0 <= 64) ? (okk[col] ? s0 * scale : NEGS) : -3.0e38f;
            S[nb][p] = s0;
            mlo = fmaxf(mlo, s0);
            float s1 = S[nb][2 + p];
            int d1 = col - rhi;
            s1 = (d1 >= 0 && d1 <= 64) ? (okk[col] ? s1 * scale : NEGS) : -3.0e38f;
            S[nb][2 + p] = s1;
            mhi = fmaxf(mhi, s1);
        }
    }
#pragma unroll
    for (int o = 1; o <= 2; o <<= 1) {
        mlo = fmaxf(mlo, __shfl_xor_sync(0xffffffffu, mlo, o));
        mhi = fmaxf(mhi, __shfl_xor_sync(0xffffffffu, mhi, o));
    }
    float slo = 0.f, shi = 0.f;
#pragma unroll
    for (int nb = 0; nb < 16; ++nb) {
#pragma unroll
        for (int p = 0; p < 2; ++p) {
            float e0 = __expf(S[nb][p] - mlo);     S[nb][p] = e0;     slo += e0;
            float e1 = __expf(S[nb][2 + p] - mhi); S[nb][2 + p] = e1; shi += e1;
        }
    }
#pragma unroll
    for (int o = 1; o <= 2; o <<= 1) {
        slo += __shfl_xor_sync(0xffffffffu, slo, o);
        shi += __shfl_xor_sync(0xffffffffu, shi, o);
    }
    const float invlo = 1.0f / slo;
    const float invhi = 1.0f / shi;

    uint32_t ph[8][4], pl[8][4];
#pragma unroll
    for (int kb = 0; kb < 8; ++kb) {
        hilo2(S[2 * kb][0] * invlo,     S[2 * kb][1] * invlo,     ph[kb][0], pl[kb][0]);
        hilo2(S[2 * kb][2] * invhi,     S[2 * kb][3] * invhi,     ph[kb][1], pl[kb][1]);
        hilo2(S[2 * kb + 1][0] * invlo, S[2 * kb + 1][1] * invlo, ph[kb][2], pl[kb][2]);
        hilo2(S[2 * kb + 1][2] * invhi, S[2 * kb + 1][3] * invhi, ph[kb][3], pl[kb][3]);
    }

    float O[8][4];
#pragma unroll
    for (int i = 0; i < 8; ++i)
#pragma unroll
        for (int j = 0; j < 4; ++j) O[i][j] = 0.0f;

    {
        uint32_t voff = (uint32_t)((lane & 15) * AROWB + (lane >> 4) * 16);
#pragma unroll
        for (int kb = 0; kb < 8; ++kb) {
            uint32_t base = voff + kb * 16 * AROWB;
#pragma unroll
            for (int db = 0; db < 4; ++db) {
                uint32_t vh0, vh1, vh2, vh3, vl0, vl1, vl2, vl3;
                LDSM_X4_T(vh0, vh1, vh2, vh3, sb + S_VH + base + db * 32);
                LDSM_X4_T(vl0, vl1, vl2, vl3, sb + S_VL + base + db * 32);
                mma_bf16(O[2 * db],     ph[kb], vh0, vh1);
                mma_bf16(O[2 * db],     ph[kb], vl0, vl1);
                mma_bf16(O[2 * db],     pl[kb], vh0, vh1);
                mma_bf16(O[2 * db + 1], ph[kb], vh2, vh3);
                mma_bf16(O[2 * db + 1], ph[kb], vl2, vl3);
                mma_bf16(O[2 * db + 1], pl[kb], vh2, vh3);
            }
        }
    }

    const size_t rowlo = (size_t)(b * L_ + q0 + rlo);
    const size_t rowhi = rowlo + 8;
#pragma unroll
    for (int nb = 0; nb < 8; ++nb) {
        int col = h * 64 + nb * 8 + (lane & 3) * 2;
        uint32_t h0, l0, h1, l1;
        hilo2(O[nb][0], O[nb][1], h0, l0);
        hilo2(O[nb][2], O[nb][3], h1, l1);
        Oh[rowlo * (E_ / 2) + (col >> 1)] = h0;
        Ol[rowlo * (E_ / 2) + (col >> 1)] = l0;
        Oh[rowhi * (E_ / 2) + (col >> 1)] = h1;
        Ol[rowhi * (E_ / 2) + (col >> 1)] = l1;
    }
}

// ---------------------------------------------------------------------------
// kernel_launch
// ---------------------------------------------------------------------------
extern "C" void kernel_launch(void* const* d_in, const int* in_sizes, int n_in,
                              void* d_out, int out_size)
{
    const float* x      = (const float*)d_in[0];
    const int*   pmask  = (const int*)d_in[1];
    const float* W_qkv  = (const float*)d_in[2];
    const float* b_qkv  = (const float*)d_in[3];
    const float* W_o    = (const float*)d_in[4];
    const float* b_o    = (const float*)d_in[5];
    float* out = (float*)d_out;

    __nv_bfloat16 *qkvh, *qkvl, *xh, *xl, *oh, *ol, *wqh, *wql, *woh, *wol;
    cudaGetSymbolAddress((void**)&qkvh, g_qkvh);
    cudaGetSymbolAddress((void**)&qkvl, g_qkvl);
    cudaGetSymbolAddress((void**)&xh, g_xh);
    cudaGetSymbolAddress((void**)&xl, g_xl);
    cudaGetSymbolAddress((void**)&oh, g_oh);
    cudaGetSymbolAddress((void**)&ol, g_ol);
    cudaGetSymbolAddress((void**)&wqh, g_wqh);
    cudaGetSymbolAddress((void**)&wql, g_wql);
    cudaGetSymbolAddress((void**)&woh, g_woh);
    cudaGetSymbolAddress((void**)&wol, g_wol);

    static bool attr_done = false;
    if (!attr_done) {
        cudaFuncSetAttribute(gemm_mma<false>, cudaFuncAttributeMaxDynamicSharedMemorySize, GEMM_SMEM);
        cudaFuncSetAttribute(gemm_mma<true>,  cudaFuncAttributeMaxDynamicSharedMemorySize, GEMM_SMEM);
        cudaFuncSetAttribute(attn_mma, cudaFuncAttributeMaxDynamicSharedMemorySize, ATTN_SMEM);
        attr_done = true;
    }

    {
        int n4 = (ML_ * KD_) / 4;
        split_bf16<<<(n4 + 255) / 256, 256>>>((const float4*)x,
            (__nv_bfloat162*)xh, (__nv_bfloat162*)xl, n4);
        int w4 = (NQKV_ * KD_) / 4;
        split_bf16<<<(w4 + 255) / 256, 256>>>((const float4*)W_qkv,
            (__nv_bfloat162*)wqh, (__nv_bfloat162*)wql, w4);
        int o4 = (E_ * E_) / 4;
        split_bf16<<<(o4 + 255) / 256, 256>>>((const float4*)W_o,
            (__nv_bfloat162*)woh, (__nv_bfloat162*)wol, o4);
    }
    gemm_mma<true><<<dim3(NQKV_ / BN, ML_ / BM), GEMM_THREADS, GEMM_SMEM>>>(
        xh, xl, wqh, wql, b_qkv, nullptr,
        (uint32_t*)qkvh, (uint32_t*)qkvl, ML_, NQKV_, KD_);
    attn_mma<<<dim3(L_ / 64, H_, B_), 128, ATTN_SMEM>>>(
        qkvh, qkvl, pmask, (uint32_t*)oh, (uint32_t*)ol);
    gemm_mma<false><<<dim3(E_ / BN, ML_ / BM), GEMM_THREADS, GEMM_SMEM>>>(
        oh, ol, woh, wol, b_o, out, nullptr, nullptr, ML_, E_, KD_);
}

// round 7
// speedup vs baseline: 2.4964x; 2.4964x over previous
#include <cuda_runtime.h>
#include <cuda_fp16.h>
#include <cstdint>
#include <math.h>

// Problem constants
#define B_    2
#define L_    2048
#define E_    1024
#define H_    16
#define HD_   64
#define KD_   1024
#define NQKV_ 3072
#define ML_   (B_*L_)   // 4096

// ---------------- GEMM tiling (fp16 single product) ----------------
#define BM 128
#define BN 128
#define BK 64
#define GEMM_THREADS 256
#define ROWB 144                    // 128B data + 16B pad (conflict-free ldsm)
#define B_OFF   (128 * ROWB)
#define STAGEB  (256 * ROWB)        // 36864
#define GEMM_SMEM (2 * STAGEB)      // 73728 -> 2 CTAs/SM co-resident

// ---------------- attention tiling ----------------
#define AROWB 144
#define S_Q  0
#define S_K  (S_Q + 64*AROWB)
#define S_V  (S_K + 128*AROWB)
#define S_OK (S_V + 128*AROWB)
#define ATTN_SMEM (S_OK + 128*4)

// ---------------- scratch ----------------
__device__ __half g_qkv16[(size_t)ML_ * NQKV_];
__device__ __half g_att16[(size_t)ML_ * E_];
__device__ __half g_x16[(size_t)ML_ * KD_];
__device__ __half g_wq16[(size_t)NQKV_ * KD_];
__device__ __half g_wo16[(size_t)E_ * E_];

// ---------------- helpers ----------------
__device__ __forceinline__ uint32_t smem_u32(const void* p) {
    uint32_t a;
    asm("{ .reg .u64 t; cvta.to.shared.u64 t, %1; cvt.u32.u64 %0, t; }" : "=r"(a) : "l"(p));
    return a;
}
#define CP16(dst, src) \
    asm volatile("cp.async.cg.shared.global [%0], [%1], 16;" :: "r"(dst), "l"(src))
#define CP_COMMIT() asm volatile("cp.async.commit_group;" ::: "memory")
#define CP_WAIT(n)  asm volatile("cp.async.wait_group %0;" :: "n"(n) : "memory")

#define LDSM_X4(r0, r1, r2, r3, a) \
    asm volatile("ldmatrix.sync.aligned.m8n8.x4.shared.b16 {%0,%1,%2,%3}, [%4];" \
                 : "=r"(r0), "=r"(r1), "=r"(r2), "=r"(r3) : "r"(a))
#define LDSM_X4_T(r0, r1, r2, r3, a) \
    asm volatile("ldmatrix.sync.aligned.m8n8.x4.trans.shared.b16 {%0,%1,%2,%3}, [%4];" \
                 : "=r"(r0), "=r"(r1), "=r"(r2), "=r"(r3) : "r"(a))

__device__ __forceinline__ void mma_f16(float c[4], const uint32_t a[4],
                                        uint32_t b0, uint32_t b1) {
    asm volatile(
        "mma.sync.aligned.m16n8k16.row.col.f32.f16.f16.f32 "
        "{%0,%1,%2,%3}, {%4,%5,%6,%7}, {%8,%9}, {%0,%1,%2,%3};"
        : "+f"(c[0]), "+f"(c[1]), "+f"(c[2]), "+f"(c[3])
        : "r"(a[0]), "r"(a[1]), "r"(a[2]), "r"(a[3]), "r"(b0), "r"(b1));
}

__device__ __forceinline__ uint32_t pk_h2(float x, float y) {
    __half2 t = __floats2half2_rn(x, y);
    return *(uint32_t*)&t;
}

// ---------------------------------------------------------------------------
// C[M,N] = A[M,K](fp16) * B[N,K]^T(fp16) + bias
// F16OUT=true: fp16 out to Ch (uint32 pairs). false: fp32 out to Cf.
// 256 threads, 4x2 warp grid, warp tile 32x64, BK=64, 2-stage cp.async.
// ---------------------------------------------------------------------------
template<bool F16OUT>
__global__ __launch_bounds__(GEMM_THREADS, 2)
void gemm_mma(const __half* __restrict__ A, const __half* __restrict__ Bm,
              const float* __restrict__ bias, float* __restrict__ Cf,
              uint32_t* __restrict__ Ch, int M, int N, int K)
{
    extern __shared__ char smem[];
    const uint32_t sbase = smem_u32(smem);
    const int tid  = threadIdx.x;
    const int lane = tid & 31;
    const int wid  = tid >> 5;
    const int warp_m = wid >> 1;     // 0..3 -> rows warp_m*32
    const int warp_n = wid & 1;      // 0..1 -> cols warp_n*64
    const int bm = blockIdx.y * BM;
    const int bn = blockIdx.x * BN;
    const int NT = K / BK;

    // ---- loader: 8 chunks of 16B per stage ----
    // g = i*256 + tid; r = g>>3 (0..255: 0-127 A rows, 128-255 B rows), c = g&7
    const __half* srcp[8];
    uint32_t dsto[8];
#pragma unroll
    for (int i = 0; i < 8; ++i) {
        int g = i * 256 + tid;
        int r = g >> 3, c = g & 7;
        const __half* base = (r < 128) ? A + (size_t)(bm + r) * K
                                       : Bm + (size_t)(bn + (r - 128)) * K;
        srcp[i] = base + c * 8;
        dsto[i] = (uint32_t)(r * ROWB + c * 16);   // B_OFF == 128*ROWB
    }

    auto stage_load = [&](int stage, int kt) {
        uint32_t sb = sbase + stage * STAGEB;
        int koff = kt * BK;
#pragma unroll
        for (int i = 0; i < 8; ++i)
            CP16(sb + dsto[i], srcp[i] + koff);
    };

    const uint32_t aOff = (uint32_t)((warp_m * 32 + (lane & 15)) * ROWB + (lane >> 4) * 16);
    const uint32_t bOff = (uint32_t)(B_OFF +
        (warp_n * 64 + ((lane >> 4) << 3) + (lane & 7)) * ROWB + ((lane >> 3) & 1) * 16);

    float acc[2][8][4];
#pragma unroll
    for (int mt = 0; mt < 2; ++mt)
#pragma unroll
        for (int nt = 0; nt < 8; ++nt)
#pragma unroll
            for (int j = 0; j < 4; ++j) acc[mt][nt][j] = 0.0f;

    stage_load(0, 0); CP_COMMIT();

    for (int kt = 0; kt < NT; ++kt) {
        CP_WAIT(0);
        __syncthreads();
        if (kt + 1 < NT) { stage_load((kt + 1) & 1, kt + 1); CP_COMMIT(); }

        const uint32_t st = sbase + (kt & 1) * STAGEB;
#pragma unroll
        for (int s = 0; s < 4; ++s) {          // four k16 steps per BK=64
            uint32_t af[2][4], bf[8][2];
#pragma unroll
            for (int mt = 0; mt < 2; ++mt) {
                uint32_t a = st + aOff + mt * 16 * ROWB + s * 32;
                LDSM_X4(af[mt][0], af[mt][1], af[mt][2], af[mt][3], a);
            }
#pragma unroll
            for (int p = 0; p < 4; ++p) {
                uint32_t a = st + bOff + p * 16 * ROWB + s * 32;
                LDSM_X4(bf[2*p][0], bf[2*p][1], bf[2*p+1][0], bf[2*p+1][1], a);
            }
#pragma unroll
            for (int mt = 0; mt < 2; ++mt)
#pragma unroll
                for (int nt = 0; nt < 8; ++nt)
                    mma_f16(acc[mt][nt], af[mt], bf[nt][0], bf[nt][1]);
        }
        __syncthreads();
    }

    const int r0 = bm + warp_m * 32 + (lane >> 2);
    const int c0 = bn + warp_n * 64 + (lane & 3) * 2;
#pragma unroll
    for (int mt = 0; mt < 2; ++mt) {
#pragma unroll
        for (int nt = 0; nt < 8; ++nt) {
            int col = c0 + nt * 8;
            float bx = bias[col], by = bias[col + 1];
            float vx0 = acc[mt][nt][0] + bx, vy0 = acc[mt][nt][1] + by;
            float vx1 = acc[mt][nt][2] + bx, vy1 = acc[mt][nt][3] + by;
            int ra = r0 + mt * 16, rb = ra + 8;
            if (F16OUT) {
                Ch[(size_t)ra * (N >> 1) + (col >> 1)] = pk_h2(vx0, vy0);
                Ch[(size_t)rb * (N >> 1) + (col >> 1)] = pk_h2(vx1, vy1);
            } else {
                *(float2*)(Cf + (size_t)ra * N + col) = make_float2(vx0, vy0);
                *(float2*)(Cf + (size_t)rb * N + col) = make_float2(vx1, vy1);
            }
        }
    }
}

// ---------------------------------------------------------------------------
// fp32 -> fp16 convert
// ---------------------------------------------------------------------------
__global__ __launch_bounds__(256) void tohalf(
    const float4* __restrict__ src, uint2* __restrict__ dst, int n4)
{
    int i = blockIdx.x * blockDim.x + threadIdx.x;
    if (i >= n4) return;
    float4 v = src[i];
    dst[i] = make_uint2(pk_h2(v.x, v.y), pk_h2(v.z, v.w));
}

// ---------------------------------------------------------------------------
// Tensor-core sliding-window attention, fp16 single product.
// Grid (L/64, H, B), 128 threads (4 warps). Warp w: q rows w*16..+15.
// ---------------------------------------------------------------------------
__global__ __launch_bounds__(128, 1) void attn_mma(
    const __half* __restrict__ qkv, const int* __restrict__ pmask,
    uint32_t* __restrict__ Oh)
{
    extern __shared__ char smem[];
    const uint32_t sb = smem_u32(smem);
    const int b = blockIdx.z, h = blockIdx.y, q0 = blockIdx.x * 64;
    const int tid = threadIdx.x, lane = tid & 31, w = tid >> 5;

    // stage Q (64 rows) and K/V (128 rows, bounds-checked)
    for (int i = tid; i < 64 * 8; i += 128) {
        int r = i >> 3, c = i & 7;
        size_t g = (size_t)(b * L_ + q0 + r) * NQKV_ + h * 192 + c * 8;
        *(uint4*)(smem + S_Q + r * AROWB + c * 16) = *(const uint4*)(qkv + g);
    }
    for (int i = tid; i < 128 * 8; i += 128) {
        int r = i >> 3, c = i & 7;
        int pos = q0 - 32 + r;
        uint4 kv = make_uint4(0, 0, 0, 0), vv = make_uint4(0, 0, 0, 0);
        if (pos >= 0 && pos < L_) {
            size_t g = (size_t)(b * L_ + pos) * NQKV_ + h * 192 + c * 8;
            kv = *(const uint4*)(qkv + g + 64);
            vv = *(const uint4*)(qkv + g + 128);
        }
        *(uint4*)(smem + S_K + r * AROWB + c * 16) = kv;
        *(uint4*)(smem + S_V + r * AROWB + c * 16) = vv;
    }
    {
        int pos = q0 - 32 + tid;
        int ok = 0;
        if (pos >= 0 && pos < L_) ok = (pmask[b * L_ + pos] != 0);
        ((int*)(smem + S_OK))[tid] = ok;
    }
    __syncthreads();
    const int* okk = (const int*)(smem + S_OK);

    // ---- S = Q K^T ----
    float S[16][4];
#pragma unroll
    for (int i = 0; i < 16; ++i)
#pragma unroll
        for (int j = 0; j < 4; ++j) S[i][j] = 0.0f;

    uint32_t qf[4][4];
    {
        uint32_t aoff = (uint32_t)((w * 16 + (lane & 15)) * AROWB + (lane >> 4) * 16);
#pragma unroll
        for (int ks = 0; ks < 4; ++ks)
            LDSM_X4(qf[ks][0], qf[ks][1], qf[ks][2], qf[ks][3], sb + S_Q + aoff + ks * 32);
    }
    {
        uint32_t boff = (uint32_t)(((((lane >> 4) << 3) + (lane & 7)) * AROWB) + ((lane >> 3) & 1) * 16);
#pragma unroll
        for (int kb = 0; kb < 8; ++kb) {
            uint32_t base = boff + kb * 16 * AROWB;
#pragma unroll
            for (int ks = 0; ks < 4; ++ks) {
                uint32_t b0, b1, b2, b3;
                LDSM_X4(b0, b1, b2, b3, sb + S_K + base + ks * 32);
                mma_f16(S[2 * kb],     qf[ks], b0, b1);
                mma_f16(S[2 * kb + 1], qf[ks], b2, b3);
            }
        }
    }

    // ---- mask + softmax (reference semantics: NEG=-1e5 then /8) ----
    const int rlo = w * 16 + (lane >> 2);
    const int rhi = rlo + 8;
    const float scale = 0.125f;
    const float NEGS = -12500.0f;
    float mlo = -3.0e38f, mhi = -3.0e38f;
#pragma unroll
    for (int nb = 0; nb < 16; ++nb) {
#pragma unroll
        for (int p = 0; p < 2; ++p) {
            int col = nb * 8 + (lane & 3) * 2 + p;
            float s0 = S[nb][p];
            int d0 = col - rlo;
            s0 = (d0 >= 0 && d0 <= 64) ? (okk[col] ? s0 * scale : NEGS) : -3.0e38f;
            S[nb][p] = s0;
            mlo = fmaxf(mlo, s0);
            float s1 = S[nb][2 + p];
            int d1 = col - rhi;
            s1 = (d1 >= 0 && d1 <= 64) ? (okk[col] ? s1 * scale : NEGS) : -3.0e38f;
            S[nb][2 + p] = s1;
            mhi = fmaxf(mhi, s1);
        }
    }
#pragma unroll
    for (int o = 1; o <= 2; o <<= 1) {
        mlo = fmaxf(mlo, __shfl_xor_sync(0xffffffffu, mlo, o));
        mhi = fmaxf(mhi, __shfl_xor_sync(0xffffffffu, mhi, o));
    }
    float slo = 0.f, shi = 0.f;
#pragma unroll
    for (int nb = 0; nb < 16; ++nb) {
#pragma unroll
        for (int p = 0; p < 2; ++p) {
            float e0 = __expf(S[nb][p] - mlo);     S[nb][p] = e0;     slo += e0;
            float e1 = __expf(S[nb][2 + p] - mhi); S[nb][2 + p] = e1; shi += e1;
        }
    }
#pragma unroll
    for (int o = 1; o <= 2; o <<= 1) {
        slo += __shfl_xor_sync(0xffffffffu, slo, o);
        shi += __shfl_xor_sync(0xffffffffu, shi, o);
    }
    const float invlo = 1.0f / slo;
    const float invhi = 1.0f / shi;

    // ---- P fragments (fp16) ----
    uint32_t pf[8][4];
#pragma unroll
    for (int kb = 0; kb < 8; ++kb) {
        pf[kb][0] = pk_h2(S[2 * kb][0] * invlo,     S[2 * kb][1] * invlo);
        pf[kb][1] = pk_h2(S[2 * kb][2] * invhi,     S[2 * kb][3] * invhi);
        pf[kb][2] = pk_h2(S[2 * kb + 1][0] * invlo, S[2 * kb + 1][1] * invlo);
        pf[kb][3] = pk_h2(S[2 * kb + 1][2] * invhi, S[2 * kb + 1][3] * invhi);
    }

    // ---- O = P V ----
    float O[8][4];
#pragma unroll
    for (int i = 0; i < 8; ++i)
#pragma unroll
        for (int j = 0; j < 4; ++j) O[i][j] = 0.0f;

    {
        uint32_t voff = (uint32_t)((lane & 15) * AROWB + (lane >> 4) * 16);
#pragma unroll
        for (int kb = 0; kb < 8; ++kb) {
            uint32_t base = voff + kb * 16 * AROWB;
#pragma unroll
            for (int db = 0; db < 4; ++db) {
                uint32_t v0, v1, v2, v3;
                LDSM_X4_T(v0, v1, v2, v3, sb + S_V + base + db * 32);
                mma_f16(O[2 * db],     pf[kb], v0, v1);
                mma_f16(O[2 * db + 1], pf[kb], v2, v3);
            }
        }
    }

    // ---- write O as fp16 [ML, E] ----
    const size_t rowlo = (size_t)(b * L_ + q0 + rlo);
    const size_t rowhi = rowlo + 8;
#pragma unroll
    for (int nb = 0; nb < 8; ++nb) {
        int col = h * 64 + nb * 8 + (lane & 3) * 2;
        Oh[rowlo * (E_ / 2) + (col >> 1)] = pk_h2(O[nb][0], O[nb][1]);
        Oh[rowhi * (E_ / 2) + (col >> 1)] = pk_h2(O[nb][2], O[nb][3]);
    }
}

// ---------------------------------------------------------------------------
// kernel_launch
// ---------------------------------------------------------------------------
extern "C" void kernel_launch(void* const* d_in, const int* in_sizes, int n_in,
                              void* d_out, int out_size)
{
    const float* x      = (const float*)d_in[0];
    const int*   pmask  = (const int*)d_in[1];
    const float* W_qkv  = (const float*)d_in[2];
    const float* b_qkv  = (const float*)d_in[3];
    const float* W_o    = (const float*)d_in[4];
    const float* b_o    = (const float*)d_in[5];
    float* out = (float*)d_out;

    __half *qkv16, *att16, *x16, *wq16, *wo16;
    cudaGetSymbolAddress((void**)&qkv16, g_qkv16);
    cudaGetSymbolAddress((void**)&att16, g_att16);
    cudaGetSymbolAddress((void**)&x16, g_x16);
    cudaGetSymbolAddress((void**)&wq16, g_wq16);
    cudaGetSymbolAddress((void**)&wo16, g_wo16);

    static bool attr_done = false;
    if (!attr_done) {
        cudaFuncSetAttribute(gemm_mma<false>, cudaFuncAttributeMaxDynamicSharedMemorySize, GEMM_SMEM);
        cudaFuncSetAttribute(gemm_mma<true>,  cudaFuncAttributeMaxDynamicSharedMemorySize, GEMM_SMEM);
        cudaFuncSetAttribute(attn_mma, cudaFuncAttributeMaxDynamicSharedMemorySize, ATTN_SMEM);
        attr_done = true;
    }

    // 1) fp32 -> fp16 converts
    {
        int n4 = (ML_ * KD_) / 4;
        tohalf<<<(n4 + 255) / 256, 256>>>((const float4*)x, (uint2*)x16, n4);
        int w4 = (NQKV_ * KD_) / 4;
        tohalf<<<(w4 + 255) / 256, 256>>>((const float4*)W_qkv, (uint2*)wq16, w4);
        int o4 = (E_ * E_) / 4;
        tohalf<<<(o4 + 255) / 256, 256>>>((const float4*)W_o, (uint2*)wo16, o4);
    }
    // 2) QKV projection -> fp16
    gemm_mma<true><<<dim3(NQKV_ / BN, ML_ / BM), GEMM_THREADS, GEMM_SMEM>>>(
        x16, wq16, b_qkv, nullptr, (uint32_t*)qkv16, ML_, NQKV_, KD_);
    // 3) attention -> fp16
    attn_mma<<<dim3(L_ / 64, H_, B_), 128, ATTN_SMEM>>>(
        qkv16, pmask, (uint32_t*)att16);
    // 4) output projection -> fp32
    gemm_mma<false><<<dim3(E_ / BN, ML_ / BM), GEMM_THREADS, GEMM_SMEM>>>(
        att16, wo16, b_o, out, nullptr, ML_, E_, KD_);
}

// round 8
// speedup vs baseline: 2.5563x; 1.0240x over previous
#include <cuda_runtime.h>
#include <cuda_fp16.h>
#include <cstdint>
#include <math.h>

// Problem constants
#define B_    2
#define L_    2048
#define E_    1024
#define H_    16
#define HD_   64
#define KD_   1024
#define NQKV_ 3072
#define ML_   (B_*L_)   // 4096

// ---------------- GEMM tiling (fp16 single product) ----------------
#define BM 128
#define BN 128
#define BK 64
#define GEMM_THREADS 256
#define ROWB 144                    // 128B data + 16B pad (conflict-free ldsm)
#define B_OFF   (128 * ROWB)
#define STAGEB  (256 * ROWB)        // 36864
#define GEMM_SMEM (2 * STAGEB)      // 73728 -> 2 CTAs/SM co-resident
#define MAX_CTAS 296                // 148 SMs * 2

// ---------------- attention tiling ----------------
#define AROWB 144
#define S_Q  0
#define S_K  (S_Q + 64*AROWB)
#define S_V  (S_K + 128*AROWB)
#define S_OK (S_V + 128*AROWB)
#define ATTN_SMEM (S_OK + 128*4)

// ---------------- scratch ----------------
__device__ __half g_qkv16[(size_t)ML_ * NQKV_];
__device__ __half g_att16[(size_t)ML_ * E_];
__device__ __half g_x16[(size_t)ML_ * KD_];
__device__ __half g_wq16[(size_t)NQKV_ * KD_];
__device__ __half g_wo16[(size_t)E_ * E_];
__device__ unsigned g_ticks[2];

// ---------------- helpers ----------------
__device__ __forceinline__ uint32_t smem_u32(const void* p) {
    uint32_t a;
    asm("{ .reg .u64 t; cvta.to.shared.u64 t, %1; cvt.u32.u64 %0, t; }" : "=r"(a) : "l"(p));
    return a;
}
#define CP16(dst, src) \
    asm volatile("cp.async.cg.shared.global [%0], [%1], 16;" :: "r"(dst), "l"(src))
#define CP_COMMIT() asm volatile("cp.async.commit_group;" ::: "memory")
#define CP_WAIT(n)  asm volatile("cp.async.wait_group %0;" :: "n"(n) : "memory")

#define LDSM_X4(r0, r1, r2, r3, a) \
    asm volatile("ldmatrix.sync.aligned.m8n8.x4.shared.b16 {%0,%1,%2,%3}, [%4];" \
                 : "=r"(r0), "=r"(r1), "=r"(r2), "=r"(r3) : "r"(a))
#define LDSM_X4_T(r0, r1, r2, r3, a) \
    asm volatile("ldmatrix.sync.aligned.m8n8.x4.trans.shared.b16 {%0,%1,%2,%3}, [%4];" \
                 : "=r"(r0), "=r"(r1), "=r"(r2), "=r"(r3) : "r"(a))

__device__ __forceinline__ void mma_f16(float c[4], const uint32_t a[4],
                                        uint32_t b0, uint32_t b1) {
    asm volatile(
        "mma.sync.aligned.m16n8k16.row.col.f32.f16.f16.f32 "
        "{%0,%1,%2,%3}, {%4,%5,%6,%7}, {%8,%9}, {%0,%1,%2,%3};"
        : "+f"(c[0]), "+f"(c[1]), "+f"(c[2]), "+f"(c[3])
        : "r"(a[0]), "r"(a[1]), "r"(a[2]), "r"(a[3]), "r"(b0), "r"(b1));
}

__device__ __forceinline__ uint32_t pk_h2(float x, float y) {
    __half2 t = __floats2half2_rn(x, y);
    return *(uint32_t*)&t;
}

// ---------------------------------------------------------------------------
// Reset work-stealing counters (per launch; graph-capturable)
// ---------------------------------------------------------------------------
__global__ void reset_ticks() { g_ticks[0] = 0; g_ticks[1] = 0; }

// ---------------------------------------------------------------------------
// Persistent work-stealing GEMM: C[M,N] = A[M,K] * B[N,K]^T + bias
// F16OUT=true: fp16 out. 256 threads, 4x2 warp grid, warp tile 32x64.
// ---------------------------------------------------------------------------
template<bool F16OUT>
__global__ __launch_bounds__(GEMM_THREADS, 2)
void gemm_mma(const __half* __restrict__ A, const __half* __restrict__ Bm,
              const float* __restrict__ bias, float* __restrict__ Cf,
              uint32_t* __restrict__ Ch, unsigned* __restrict__ tick,
              int M, int N, int K, int ntiles)
{
    extern __shared__ char smem[];
    __shared__ unsigned s_tile;
    const uint32_t sbase = smem_u32(smem);
    const int tid  = threadIdx.x;
    const int lane = tid & 31;
    const int wid  = tid >> 5;
    const int warp_m = wid >> 1;
    const int warp_n = wid & 1;
    const int NT = K / BK;
    const int nbn = N / BN;

    // per-thread load geometry (tile-independent): chunks i=0..3 -> A, 4..7 -> B
    const int tr = tid >> 3;        // 0..31
    const int lc = tid & 7;
    size_t offA[4], offB[4];
    uint32_t dstA[4], dstB[4];
#pragma unroll
    for (int i = 0; i < 4; ++i) {
        int ra = i * 32 + tr;                       // 0..127
        offA[i] = (size_t)ra * K + lc * 8;
        dstA[i] = (uint32_t)(ra * ROWB + lc * 16);
        offB[i] = (size_t)ra * K + lc * 8;          // B local row = same pattern
        dstB[i] = (uint32_t)(ra * ROWB + lc * 16) + B_OFF;
    }

    const uint32_t aOff = (uint32_t)((warp_m * 32 + (lane & 15)) * ROWB + (lane >> 4) * 16);
    const uint32_t bOff = (uint32_t)(B_OFF +
        (warp_n * 64 + ((lane >> 4) << 3) + (lane & 7)) * ROWB + ((lane >> 3) & 1) * 16);

    for (;;) {
        __syncthreads();                       // smem/s_tile reuse safety
        if (tid == 0) s_tile = atomicAdd(tick, 1u);
        __syncthreads();
        const unsigned t = s_tile;
        if (t >= (unsigned)ntiles) break;
        const int bm = (int)(t / nbn) * BM;
        const int bn = (int)(t % nbn) * BN;
        const __half* Abase = A + (size_t)bm * K;
        const __half* Bbase = Bm + (size_t)bn * K;

        float acc[2][8][4];
#pragma unroll
        for (int mt = 0; mt < 2; ++mt)
#pragma unroll
            for (int nt = 0; nt < 8; ++nt)
#pragma unroll
                for (int j = 0; j < 4; ++j) acc[mt][nt][j] = 0.0f;

        // prologue: stage 0
        {
            uint32_t sb = sbase;
#pragma unroll
            for (int i = 0; i < 4; ++i) {
                CP16(sb + dstA[i], Abase + offA[i]);
                CP16(sb + dstB[i], Bbase + offB[i]);
            }
            CP_COMMIT();
        }

        for (int kt = 0; kt < NT; ++kt) {
            CP_WAIT(0);
            __syncthreads();
            if (kt + 1 < NT) {
                uint32_t sb = sbase + ((kt + 1) & 1) * STAGEB;
                int koff = (kt + 1) * BK;
#pragma unroll
                for (int i = 0; i < 4; ++i) {
                    CP16(sb + dstA[i], Abase + offA[i] + koff);
                    CP16(sb + dstB[i], Bbase + offB[i] + koff);
                }
                CP_COMMIT();
            }

            const uint32_t st = sbase + (kt & 1) * STAGEB;
#pragma unroll
            for (int s = 0; s < 4; ++s) {
                uint32_t af[2][4], bf[8][2];
#pragma unroll
                for (int mt = 0; mt < 2; ++mt) {
                    uint32_t a = st + aOff + mt * 16 * ROWB + s * 32;
                    LDSM_X4(af[mt][0], af[mt][1], af[mt][2], af[mt][3], a);
                }
#pragma unroll
                for (int p = 0; p < 4; ++p) {
                    uint32_t a = st + bOff + p * 16 * ROWB + s * 32;
                    LDSM_X4(bf[2*p][0], bf[2*p][1], bf[2*p+1][0], bf[2*p+1][1], a);
                }
#pragma unroll
                for (int mt = 0; mt < 2; ++mt)
#pragma unroll
                    for (int nt = 0; nt < 8; ++nt)
                        mma_f16(acc[mt][nt], af[mt], bf[nt][0], bf[nt][1]);
            }
            __syncthreads();
        }

        const int r0 = bm + warp_m * 32 + (lane >> 2);
        const int c0 = bn + warp_n * 64 + (lane & 3) * 2;
#pragma unroll
        for (int mt = 0; mt < 2; ++mt) {
#pragma unroll
            for (int nt = 0; nt < 8; ++nt) {
                int col = c0 + nt * 8;
                float bx = bias[col], by = bias[col + 1];
                float vx0 = acc[mt][nt][0] + bx, vy0 = acc[mt][nt][1] + by;
                float vx1 = acc[mt][nt][2] + bx, vy1 = acc[mt][nt][3] + by;
                int ra = r0 + mt * 16, rb = ra + 8;
                if (F16OUT) {
                    Ch[(size_t)ra * (N >> 1) + (col >> 1)] = pk_h2(vx0, vy0);
                    Ch[(size_t)rb * (N >> 1) + (col >> 1)] = pk_h2(vx1, vy1);
                } else {
                    *(float2*)(Cf + (size_t)ra * N + col) = make_float2(vx0, vy0);
                    *(float2*)(Cf + (size_t)rb * N + col) = make_float2(vx1, vy1);
                }
            }
        }
    }
}

// ---------------------------------------------------------------------------
// fp32 -> fp16 convert, all three tensors in one launch
// ---------------------------------------------------------------------------
__global__ __launch_bounds__(256) void tohalf3(
    const float4* __restrict__ s0, uint2* __restrict__ d0, int n0,
    const float4* __restrict__ s1, uint2* __restrict__ d1, int n1,
    const float4* __restrict__ s2, uint2* __restrict__ d2, int n2)
{
    int i = blockIdx.x * blockDim.x + threadIdx.x;
    const float4* s; uint2* d;
    if (i < n0)           { s = s0 + i; d = d0 + i; }
    else if (i < n0 + n1) { s = s1 + (i - n0); d = d1 + (i - n0); }
    else if (i < n0 + n1 + n2) { s = s2 + (i - n0 - n1); d = d2 + (i - n0 - n1); }
    else return;
    float4 v = *s;
    *d = make_uint2(pk_h2(v.x, v.y), pk_h2(v.z, v.w));
}

// ---------------------------------------------------------------------------
// Tensor-core sliding-window attention, fp16 single product (unchanged).
// ---------------------------------------------------------------------------
__global__ __launch_bounds__(128, 1) void attn_mma(
    const __half* __restrict__ qkv, const int* __restrict__ pmask,
    uint32_t* __restrict__ Oh)
{
    extern __shared__ char smem[];
    const uint32_t sb = smem_u32(smem);
    const int b = blockIdx.z, h = blockIdx.y, q0 = blockIdx.x * 64;
    const int tid = threadIdx.x, lane = tid & 31, w = tid >> 5;

    for (int i = tid; i < 64 * 8; i += 128) {
        int r = i >> 3, c = i & 7;
        size_t g = (size_t)(b * L_ + q0 + r) * NQKV_ + h * 192 + c * 8;
        *(uint4*)(smem + S_Q + r * AROWB + c * 16) = *(const uint4*)(qkv + g);
    }
    for (int i = tid; i < 128 * 8; i += 128) {
        int r = i >> 3, c = i & 7;
        int pos = q0 - 32 + r;
        uint4 kv = make_uint4(0, 0, 0, 0), vv = make_uint4(0, 0, 0, 0);
        if (pos >= 0 && pos < L_) {
            size_t g = (size_t)(b * L_ + pos) * NQKV_ + h * 192 + c * 8;
            kv = *(const uint4*)(qkv + g + 64);
            vv = *(const uint4*)(qkv + g + 128);
        }
        *(uint4*)(smem + S_K + r * AROWB + c * 16) = kv;
        *(uint4*)(smem + S_V + r * AROWB + c * 16) = vv;
    }
    {
        int pos = q0 - 32 + tid;
        int ok = 0;
        if (pos >= 0 && pos < L_) ok = (pmask[b * L_ + pos] != 0);
        ((int*)(smem + S_OK))[tid] = ok;
    }
    __syncthreads();
    const int* okk = (const int*)(smem + S_OK);

    float S[16][4];
#pragma unroll
    for (int i = 0; i < 16; ++i)
#pragma unroll
        for (int j = 0; j < 4; ++j) S[i][j] = 0.0f;

    uint32_t qf[4][4];
    {
        uint32_t aoff = (uint32_t)((w * 16 + (lane & 15)) * AROWB + (lane >> 4) * 16);
#pragma unroll
        for (int ks = 0; ks < 4; ++ks)
            LDSM_X4(qf[ks][0], qf[ks][1], qf[ks][2], qf[ks][3], sb + S_Q + aoff + ks * 32);
    }
    {
        uint32_t boff = (uint32_t)(((((lane >> 4) << 3) + (lane & 7)) * AROWB) + ((lane >> 3) & 1) * 16);
#pragma unroll
        for (int kb = 0; kb < 8; ++kb) {
            uint32_t base = boff + kb * 16 * AROWB;
#pragma unroll
            for (int ks = 0; ks < 4; ++ks) {
                uint32_t b0, b1, b2, b3;
                LDSM_X4(b0, b1, b2, b3, sb + S_K + base + ks * 32);
                mma_f16(S[2 * kb],     qf[ks], b0, b1);
                mma_f16(S[2 * kb + 1], qf[ks], b2, b3);
            }
        }
    }

    const int rlo = w * 16 + (lane >> 2);
    const int rhi = rlo + 8;
    const float scale = 0.125f;
    const float NEGS = -12500.0f;
    float mlo = -3.0e38f, mhi = -3.0e38f;
#pragma unroll
    for (int nb = 0; nb < 16; ++nb) {
#pragma unroll
        for (int p = 0; p < 2; ++p) {
            int col = nb * 8 + (lane & 3) * 2 + p;
            float s0 = S[nb][p];
            int d0 = col - rlo;
            s0 = (d0 >= 0 && d0 <= 64) ? (okk[col] ? s0 * scale : NEGS) : -3.0e38f;
            S[nb][p] = s0;
            mlo = fmaxf(mlo, s0);
            float s1 = S[nb][2 + p];
            int d1 = col - rhi;
            s1 = (d1 >= 0 && d1 <= 64) ? (okk[col] ? s1 * scale : NEGS) : -3.0e38f;
            S[nb][2 + p] = s1;
            mhi = fmaxf(mhi, s1);
        }
    }
#pragma unroll
    for (int o = 1; o <= 2; o <<= 1) {
        mlo = fmaxf(mlo, __shfl_xor_sync(0xffffffffu, mlo, o));
        mhi = fmaxf(mhi, __shfl_xor_sync(0xffffffffu, mhi, o));
    }
    float slo = 0.f, shi = 0.f;
#pragma unroll
    for (int nb = 0; nb < 16; ++nb) {
#pragma unroll
        for (int p = 0; p < 2; ++p) {
            float e0 = __expf(S[nb][p] - mlo);     S[nb][p] = e0;     slo += e0;
            float e1 = __expf(S[nb][2 + p] - mhi); S[nb][2 + p] = e1; shi += e1;
        }
    }
#pragma unroll
    for (int o = 1; o <= 2; o <<= 1) {
        slo += __shfl_xor_sync(0xffffffffu, slo, o);
        shi += __shfl_xor_sync(0xffffffffu, shi, o);
    }
    const float invlo = 1.0f / slo;
    const float invhi = 1.0f / shi;

    uint32_t pf[8][4];
#pragma unroll
    for (int kb = 0; kb < 8; ++kb) {
        pf[kb][0] = pk_h2(S[2 * kb][0] * invlo,     S[2 * kb][1] * invlo);
        pf[kb][1] = pk_h2(S[2 * kb][2] * invhi,     S[2 * kb][3] * invhi);
        pf[kb][2] = pk_h2(S[2 * kb + 1][0] * invlo, S[2 * kb + 1][1] * invlo);
        pf[kb][3] = pk_h2(S[2 * kb + 1][2] * invhi, S[2 * kb + 1][3] * invhi);
    }

    float O[8][4];
#pragma unroll
    for (int i = 0; i < 8; ++i)
#pragma unroll
        for (int j = 0; j < 4; ++j) O[i][j] = 0.0f;

    {
        uint32_t voff = (uint32_t)((lane & 15) * AROWB + (lane >> 4) * 16);
#pragma unroll
        for (int kb = 0; kb < 8; ++kb) {
            uint32_t base = voff + kb * 16 * AROWB;
#pragma unroll
            for (int db = 0; db < 4; ++db) {
                uint32_t v0, v1, v2, v3;
                LDSM_X4_T(v0, v1, v2, v3, sb + S_V + base + db * 32);
                mma_f16(O[2 * db],     pf[kb], v0, v1);
                mma_f16(O[2 * db + 1], pf[kb], v2, v3);
            }
        }
    }

    const size_t rowlo = (size_t)(b * L_ + q0 + rlo);
    const size_t rowhi = rowlo + 8;
#pragma unroll
    for (int nb = 0; nb < 8; ++nb) {
        int col = h * 64 + nb * 8 + (lane & 3) * 2;
        Oh[rowlo * (E_ / 2) + (col >> 1)] = pk_h2(O[nb][0], O[nb][1]);
        Oh[rowhi * (E_ / 2) + (col >> 1)] = pk_h2(O[nb][2], O[nb][3]);
    }
}

// ---------------------------------------------------------------------------
// kernel_launch
// ---------------------------------------------------------------------------
extern "C" void kernel_launch(void* const* d_in, const int* in_sizes, int n_in,
                              void* d_out, int out_size)
{
    const float* x      = (const float*)d_in[0];
    const int*   pmask  = (const int*)d_in[1];
    const float* W_qkv  = (const float*)d_in[2];
    const float* b_qkv  = (const float*)d_in[3];
    const float* W_o    = (const float*)d_in[4];
    const float* b_o    = (const float*)d_in[5];
    float* out = (float*)d_out;

    __half *qkv16, *att16, *x16, *wq16, *wo16;
    unsigned* ticks;
    cudaGetSymbolAddress((void**)&qkv16, g_qkv16);
    cudaGetSymbolAddress((void**)&att16, g_att16);
    cudaGetSymbolAddress((void**)&x16, g_x16);
    cudaGetSymbolAddress((void**)&wq16, g_wq16);
    cudaGetSymbolAddress((void**)&wo16, g_wo16);
    cudaGetSymbolAddress((void**)&ticks, g_ticks);

    static bool attr_done = false;
    if (!attr_done) {
        cudaFuncSetAttribute(gemm_mma<false>, cudaFuncAttributeMaxDynamicSharedMemorySize, GEMM_SMEM);
        cudaFuncSetAttribute(gemm_mma<true>,  cudaFuncAttributeMaxDynamicSharedMemorySize, GEMM_SMEM);
        cudaFuncSetAttribute(attn_mma, cudaFuncAttributeMaxDynamicSharedMemorySize, ATTN_SMEM);
        attr_done = true;
    }

    // 0) reset work-stealing counters
    reset_ticks<<<1, 1>>>();

    // 1) fp32 -> fp16 converts (single launch)
    {
        int n0 = (ML_ * KD_) / 4;
        int n1 = (NQKV_ * KD_) / 4;
        int n2 = (E_ * E_) / 4;
        int tot = n0 + n1 + n2;
        tohalf3<<<(tot + 255) / 256, 256>>>(
            (const float4*)x, (uint2*)x16, n0,
            (const float4*)W_qkv, (uint2*)wq16, n1,
            (const float4*)W_o, (uint2*)wo16, n2);
    }
    // 2) QKV projection -> fp16 (persistent, work-stealing)
    {
        int ntiles = (ML_ / BM) * (NQKV_ / BN);   // 768
        int grid = ntiles < MAX_CTAS ? ntiles : MAX_CTAS;
        gemm_mma<true><<<grid, GEMM_THREADS, GEMM_SMEM>>>(
            x16, wq16, b_qkv, nullptr, (uint32_t*)qkv16, ticks + 0,
            ML_, NQKV_, KD_, ntiles);
    }
    // 3) attention -> fp16
    attn_mma<<<dim3(L_ / 64, H_, B_), 128, ATTN_SMEM>>>(
        qkv16, pmask, (uint32_t*)att16);
    // 4) output projection -> fp32 (persistent, work-stealing)
    {
        int ntiles = (ML_ / BM) * (E_ / BN);      // 256
        int grid = ntiles < MAX_CTAS ? ntiles : MAX_CTAS;
        gemm_mma<false><<<grid, GEMM_THREADS, GEMM_SMEM>>>(
            att16, wo16, b_o, out, nullptr, ticks + 1,
            ML_, E_, KD_, ntiles);
    }
}

// round 9
// speedup vs baseline: 2.6208x; 1.0252x over previous
#include <cuda_runtime.h>
#include <cuda_fp16.h>
#include <cstdint>
#include <math.h>

// Problem constants
#define B_    2
#define L_    2048
#define E_    1024
#define H_    16
#define HD_   64
#define KD_   1024
#define NQKV_ 3072
#define ML_   (B_*L_)   // 4096

// ---------------- GEMM tiling (fp16 single product) ----------------
#define BM 128
#define BN 128
#define BK 64
#define GEMM_THREADS 256
#define ROWB 144                    // 128B data + 16B pad (conflict-free ldsm)
#define B_OFF   (128 * ROWB)
#define STAGEB  (256 * ROWB)        // 36864
#define GEMM_SMEM (2 * STAGEB)      // 73728 -> 2 CTAs/SM co-resident
#define MAX_CTAS 296                // 148 SMs * 2

// ---------------- attention tiling ----------------
#define AROWB 144
#define QROWS 128                   // queries per block
#define KROWS 192                   // staged K/V span
#define S_Q  0
#define S_K  (S_Q + QROWS*AROWB)
#define S_V  (S_K + KROWS*AROWB)
#define S_OK (S_V + KROWS*AROWB)
#define ATTN_SMEM (S_OK + KROWS*4)  // 74496

// ---------------- scratch ----------------
__device__ __half g_qkv16[(size_t)ML_ * NQKV_];
__device__ __half g_att16[(size_t)ML_ * E_];
__device__ __half g_x16[(size_t)ML_ * KD_];
__device__ __half g_wq16[(size_t)NQKV_ * KD_];
__device__ __half g_wo16[(size_t)E_ * E_];
__device__ unsigned g_ticks[2];

// ---------------- helpers ----------------
__device__ __forceinline__ uint32_t smem_u32(const void* p) {
    uint32_t a;
    asm("{ .reg .u64 t; cvta.to.shared.u64 t, %1; cvt.u32.u64 %0, t; }" : "=r"(a) : "l"(p));
    return a;
}
#define CP16(dst, src) \
    asm volatile("cp.async.cg.shared.global [%0], [%1], 16;" :: "r"(dst), "l"(src))
#define CP_COMMIT() asm volatile("cp.async.commit_group;" ::: "memory")
#define CP_WAIT(n)  asm volatile("cp.async.wait_group %0;" :: "n"(n) : "memory")

#define LDSM_X4(r0, r1, r2, r3, a) \
    asm volatile("ldmatrix.sync.aligned.m8n8.x4.shared.b16 {%0,%1,%2,%3}, [%4];" \
                 : "=r"(r0), "=r"(r1), "=r"(r2), "=r"(r3) : "r"(a))
#define LDSM_X4_T(r0, r1, r2, r3, a) \
    asm volatile("ldmatrix.sync.aligned.m8n8.x4.trans.shared.b16 {%0,%1,%2,%3}, [%4];" \
                 : "=r"(r0), "=r"(r1), "=r"(r2), "=r"(r3) : "r"(a))

__device__ __forceinline__ void mma_f16(float c[4], const uint32_t a[4],
                                        uint32_t b0, uint32_t b1) {
    asm volatile(
        "mma.sync.aligned.m16n8k16.row.col.f32.f16.f16.f32 "
        "{%0,%1,%2,%3}, {%4,%5,%6,%7}, {%8,%9}, {%0,%1,%2,%3};"
        : "+f"(c[0]), "+f"(c[1]), "+f"(c[2]), "+f"(c[3])
        : "r"(a[0]), "r"(a[1]), "r"(a[2]), "r"(a[3]), "r"(b0), "r"(b1));
}

__device__ __forceinline__ uint32_t pk_h2(float x, float y) {
    __half2 t = __floats2half2_rn(x, y);
    return *(uint32_t*)&t;
}

// ---------------------------------------------------------------------------
// Persistent work-stealing GEMM: C[M,N] = A[M,K] * B[N,K]^T + bias
// ---------------------------------------------------------------------------
template<bool F16OUT>
__global__ __launch_bounds__(GEMM_THREADS, 2)
void gemm_mma(const __half* __restrict__ A, const __half* __restrict__ Bm,
              const float* __restrict__ bias, float* __restrict__ Cf,
              uint32_t* __restrict__ Ch, unsigned* __restrict__ tick,
              int M, int N, int K, int ntiles)
{
    extern __shared__ char smem[];
    __shared__ unsigned s_tile;
    const uint32_t sbase = smem_u32(smem);
    const int tid  = threadIdx.x;
    const int lane = tid & 31;
    const int wid  = tid >> 5;
    const int warp_m = wid >> 1;
    const int warp_n = wid & 1;
    const int NT = K / BK;
    const int nbn = N / BN;

    const int tr = tid >> 3;
    const int lc = tid & 7;
    size_t offA[4], offB[4];
    uint32_t dstA[4], dstB[4];
#pragma unroll
    for (int i = 0; i < 4; ++i) {
        int ra = i * 32 + tr;
        offA[i] = (size_t)ra * K + lc * 8;
        dstA[i] = (uint32_t)(ra * ROWB + lc * 16);
        offB[i] = (size_t)ra * K + lc * 8;
        dstB[i] = (uint32_t)(ra * ROWB + lc * 16) + B_OFF;
    }

    const uint32_t aOff = (uint32_t)((warp_m * 32 + (lane & 15)) * ROWB + (lane >> 4) * 16);
    const uint32_t bOff = (uint32_t)(B_OFF +
        (warp_n * 64 + ((lane >> 4) << 3) + (lane & 7)) * ROWB + ((lane >> 3) & 1) * 16);

    for (;;) {
        __syncthreads();
        if (tid == 0) s_tile = atomicAdd(tick, 1u);
        __syncthreads();
        const unsigned t = s_tile;
        if (t >= (unsigned)ntiles) break;
        const int bm = (int)(t / nbn) * BM;
        const int bn = (int)(t % nbn) * BN;
        const __half* Abase = A + (size_t)bm * K;
        const __half* Bbase = Bm + (size_t)bn * K;

        float acc[2][8][4];
#pragma unroll
        for (int mt = 0; mt < 2; ++mt)
#pragma unroll
            for (int nt = 0; nt < 8; ++nt)
#pragma unroll
                for (int j = 0; j < 4; ++j) acc[mt][nt][j] = 0.0f;

        {
            uint32_t sb = sbase;
#pragma unroll
            for (int i = 0; i < 4; ++i) {
                CP16(sb + dstA[i], Abase + offA[i]);
                CP16(sb + dstB[i], Bbase + offB[i]);
            }
            CP_COMMIT();
        }

        for (int kt = 0; kt < NT; ++kt) {
            CP_WAIT(0);
            __syncthreads();
            if (kt + 1 < NT) {
                uint32_t sb = sbase + ((kt + 1) & 1) * STAGEB;
                int koff = (kt + 1) * BK;
#pragma unroll
                for (int i = 0; i < 4; ++i) {
                    CP16(sb + dstA[i], Abase + offA[i] + koff);
                    CP16(sb + dstB[i], Bbase + offB[i] + koff);
                }
                CP_COMMIT();
            }

            const uint32_t st = sbase + (kt & 1) * STAGEB;
#pragma unroll
            for (int s = 0; s < 4; ++s) {
                uint32_t af[2][4], bf[8][2];
#pragma unroll
                for (int mt = 0; mt < 2; ++mt) {
                    uint32_t a = st + aOff + mt * 16 * ROWB + s * 32;
                    LDSM_X4(af[mt][0], af[mt][1], af[mt][2], af[mt][3], a);
                }
#pragma unroll
                for (int p = 0; p < 4; ++p) {
                    uint32_t a = st + bOff + p * 16 * ROWB + s * 32;
                    LDSM_X4(bf[2*p][0], bf[2*p][1], bf[2*p+1][0], bf[2*p+1][1], a);
                }
#pragma unroll
                for (int mt = 0; mt < 2; ++mt)
#pragma unroll
                    for (int nt = 0; nt < 8; ++nt)
                        mma_f16(acc[mt][nt], af[mt], bf[nt][0], bf[nt][1]);
            }
            __syncthreads();
        }

        const int r0 = bm + warp_m * 32 + (lane >> 2);
        const int c0 = bn + warp_n * 64 + (lane & 3) * 2;
#pragma unroll
        for (int mt = 0; mt < 2; ++mt) {
#pragma unroll
            for (int nt = 0; nt < 8; ++nt) {
                int col = c0 + nt * 8;
                float bx = bias[col], by = bias[col + 1];
                float vx0 = acc[mt][nt][0] + bx, vy0 = acc[mt][nt][1] + by;
                float vx1 = acc[mt][nt][2] + bx, vy1 = acc[mt][nt][3] + by;
                int ra = r0 + mt * 16, rb = ra + 8;
                if (F16OUT) {
                    Ch[(size_t)ra * (N >> 1) + (col >> 1)] = pk_h2(vx0, vy0);
                    Ch[(size_t)rb * (N >> 1) + (col >> 1)] = pk_h2(vx1, vy1);
                } else {
                    *(float2*)(Cf + (size_t)ra * N + col) = make_float2(vx0, vy0);
                    *(float2*)(Cf + (size_t)rb * N + col) = make_float2(vx1, vy1);
                }
            }
        }
    }
}

// ---------------------------------------------------------------------------
// fp32 -> fp16 converts (one launch) + work-stealing tick reset
// ---------------------------------------------------------------------------
__global__ __launch_bounds__(256) void tohalf3(
    const float4* __restrict__ s0, uint2* __restrict__ d0, int n0,
    const float4* __restrict__ s1, uint2* __restrict__ d1, int n1,
    const float4* __restrict__ s2, uint2* __restrict__ d2, int n2,
    unsigned* __restrict__ ticks)
{
    int i = blockIdx.x * blockDim.x + threadIdx.x;
    if (i == 0) { ticks[0] = 0; ticks[1] = 0; }
    const float4* s; uint2* d;
    if (i < n0)           { s = s0 + i; d = d0 + i; }
    else if (i < n0 + n1) { s = s1 + (i - n0); d = d1 + (i - n0); }
    else if (i < n0 + n1 + n2) { s = s2 + (i - n0 - n1); d = d2 + (i - n0 - n1); }
    else return;
    float4 v = *s;
    *d = make_uint2(pk_h2(v.x, v.y), pk_h2(v.z, v.w));
}

// ---------------------------------------------------------------------------
// Band-skipping tensor-core sliding-window attention.
// Grid (L/128, H, B), 256 threads (8 warps). Warp w: queries 16w..16w+15
// (local). Staged K/V span 192 rows (pos q0-32 .. q0+159). For warp w only
// key blocks kb in [w, w+4] intersect the window band -> 40 S-MMAs + 40
// PV-MMAs per warp instead of 64+64. Numerically identical to full compute.
// ---------------------------------------------------------------------------
__global__ __launch_bounds__(256, 1) void attn_mma(
    const __half* __restrict__ qkv, const int* __restrict__ pmask,
    uint32_t* __restrict__ Oh)
{
    extern __shared__ char smem[];
    const uint32_t sb = smem_u32(smem);
    const int b = blockIdx.z, h = blockIdx.y, q0 = blockIdx.x * QROWS;
    const int tid = threadIdx.x, lane = tid & 31, w = tid >> 5;

    // stage Q (128 rows)
    for (int i = tid; i < QROWS * 8; i += 256) {
        int r = i >> 3, c = i & 7;
        size_t g = (size_t)(b * L_ + q0 + r) * NQKV_ + h * 192 + c * 8;
        *(uint4*)(smem + S_Q + r * AROWB + c * 16) = *(const uint4*)(qkv + g);
    }
    // stage K/V (192 rows: pos q0-32+r, bounds-checked)
    for (int i = tid; i < KROWS * 8; i += 256) {
        int r = i >> 3, c = i & 7;
        int pos = q0 - 32 + r;
        uint4 kv = make_uint4(0, 0, 0, 0), vv = make_uint4(0, 0, 0, 0);
        if (pos >= 0 && pos < L_) {
            size_t g = (size_t)(b * L_ + pos) * NQKV_ + h * 192 + c * 8;
            kv = *(const uint4*)(qkv + g + 64);
            vv = *(const uint4*)(qkv + g + 128);
        }
        *(uint4*)(smem + S_K + r * AROWB + c * 16) = kv;
        *(uint4*)(smem + S_V + r * AROWB + c * 16) = vv;
    }
    if (tid < KROWS) {
        int pos = q0 - 32 + tid;
        int ok = (pos >= 0 && pos < L_) ? (pmask[b * L_ + pos] != 0) : 0;
        ((int*)(smem + S_OK))[tid] = ok;
    }
    __syncthreads();
    const int* okk = (const int*)(smem + S_OK);

    // ---- S = Q K^T over the band ----
    float S[10][4];
#pragma unroll
    for (int i = 0; i < 10; ++i)
#pragma unroll
        for (int j = 0; j < 4; ++j) S[i][j] = 0.0f;

    uint32_t qf[4][4];
    {
        uint32_t aoff = (uint32_t)((w * 16 + (lane & 15)) * AROWB + (lane >> 4) * 16);
#pragma unroll
        for (int ks = 0; ks < 4; ++ks)
            LDSM_X4(qf[ks][0], qf[ks][1], qf[ks][2], qf[ks][3], sb + S_Q + aoff + ks * 32);
    }
    {
        uint32_t boff = (uint32_t)(((((lane >> 4) << 3) + (lane & 7)) * AROWB) + ((lane >> 3) & 1) * 16);
#pragma unroll
        for (int kbl = 0; kbl < 5; ++kbl) {
            uint32_t base = boff + (w + kbl) * 16 * AROWB;
#pragma unroll
            for (int ks = 0; ks < 4; ++ks) {
                uint32_t b0, b1, b2, b3;
                LDSM_X4(b0, b1, b2, b3, sb + S_K + base + ks * 32);
                mma_f16(S[2 * kbl],     qf[ks], b0, b1);
                mma_f16(S[2 * kbl + 1], qf[ks], b2, b3);
            }
        }
    }

    // ---- mask + softmax (reference semantics: NEG=-1e5 then /8) ----
    const int qlo = w * 16 + (lane >> 2);     // local query row (lo half)
    const float scale = 0.125f;
    const float NEGS = -12500.0f;
    float mlo = -3.0e38f, mhi = -3.0e38f;
#pragma unroll
    for (int nbl = 0; nbl < 10; ++nbl) {
        int kbl = nbl >> 1, grp = nbl & 1;
#pragma unroll
        for (int p = 0; p < 2; ++p) {
            int j = (w + kbl) * 16 + grp * 8 + (lane & 3) * 2 + p;  // local key row
            float s0 = S[nbl][p];
            int d0 = j - qlo;
            s0 = (d0 >= 0 && d0 <= 64) ? (okk[j] ? s0 * scale : NEGS) : -3.0e38f;
            S[nbl][p] = s0;
            mlo = fmaxf(mlo, s0);
            float s1 = S[nbl][2 + p];
            int d1 = j - (qlo + 8);
            s1 = (d1 >= 0 && d1 <= 64) ? (okk[j] ? s1 * scale : NEGS) : -3.0e38f;
            S[nbl][2 + p] = s1;
            mhi = fmaxf(mhi, s1);
        }
    }
#pragma unroll
    for (int o = 1; o <= 2; o <<= 1) {
        mlo = fmaxf(mlo, __shfl_xor_sync(0xffffffffu, mlo, o));
        mhi = fmaxf(mhi, __shfl_xor_sync(0xffffffffu, mhi, o));
    }
    float slo = 0.f, shi = 0.f;
#pragma unroll
    for (int nbl = 0; nbl < 10; ++nbl) {
#pragma unroll
        for (int p = 0; p < 2; ++p) {
            float e0 = __expf(S[nbl][p] - mlo);     S[nbl][p] = e0;     slo += e0;
            float e1 = __expf(S[nbl][2 + p] - mhi); S[nbl][2 + p] = e1; shi += e1;
        }
    }
#pragma unroll
    for (int o = 1; o <= 2; o <<= 1) {
        slo += __shfl_xor_sync(0xffffffffu, slo, o);
        shi += __shfl_xor_sync(0xffffffffu, shi, o);
    }
    const float invlo = 1.0f / slo;
    const float invhi = 1.0f / shi;

    // ---- P fragments (fp16) ----
    uint32_t pf[5][4];
#pragma unroll
    for (int kbl = 0; kbl < 5; ++kbl) {
        pf[kbl][0] = pk_h2(S[2 * kbl][0] * invlo,     S[2 * kbl][1] * invlo);
        pf[kbl][1] = pk_h2(S[2 * kbl][2] * invhi,     S[2 * kbl][3] * invhi);
        pf[kbl][2] = pk_h2(S[2 * kbl + 1][0] * invlo, S[2 * kbl + 1][1] * invlo);
        pf[kbl][3] = pk_h2(S[2 * kbl + 1][2] * invhi, S[2 * kbl + 1][3] * invhi);
    }

    // ---- O = P V over the band ----
    float O[8][4];
#pragma unroll
    for (int i = 0; i < 8; ++i)
#pragma unroll
        for (int j = 0; j < 4; ++j) O[i][j] = 0.0f;

    {
        uint32_t voff = (uint32_t)((lane & 15) * AROWB + (lane >> 4) * 16);
#pragma unroll
        for (int kbl = 0; kbl < 5; ++kbl) {
            uint32_t base = voff + (w + kbl) * 16 * AROWB;
#pragma unroll
            for (int db = 0; db < 4; ++db) {
                uint32_t v0, v1, v2, v3;
                LDSM_X4_T(v0, v1, v2, v3, sb + S_V + base + db * 32);
                mma_f16(O[2 * db],     pf[kbl], v0, v1);
                mma_f16(O[2 * db + 1], pf[kbl], v2, v3);
            }
        }
    }

    // ---- write O as fp16 [ML, E] ----
    const size_t rowlo = (size_t)(b * L_ + q0 + qlo);
    const size_t rowhi = rowlo + 8;
#pragma unroll
    for (int nb = 0; nb < 8; ++nb) {
        int col = h * 64 + nb * 8 + (lane & 3) * 2;
        Oh[rowlo * (E_ / 2) + (col >> 1)] = pk_h2(O[nb][0], O[nb][1]);
        Oh[rowhi * (E_ / 2) + (col >> 1)] = pk_h2(O[nb][2], O[nb][3]);
    }
}

// ---------------------------------------------------------------------------
// kernel_launch
// ---------------------------------------------------------------------------
extern "C" void kernel_launch(void* const* d_in, const int* in_sizes, int n_in,
                              void* d_out, int out_size)
{
    const float* x      = (const float*)d_in[0];
    const int*   pmask  = (const int*)d_in[1];
    const float* W_qkv  = (const float*)d_in[2];
    const float* b_qkv  = (const float*)d_in[3];
    const float* W_o    = (const float*)d_in[4];
    const float* b_o    = (const float*)d_in[5];
    float* out = (float*)d_out;

    __half *qkv16, *att16, *x16, *wq16, *wo16;
    unsigned* ticks;
    cudaGetSymbolAddress((void**)&qkv16, g_qkv16);
    cudaGetSymbolAddress((void**)&att16, g_att16);
    cudaGetSymbolAddress((void**)&x16, g_x16);
    cudaGetSymbolAddress((void**)&wq16, g_wq16);
    cudaGetSymbolAddress((void**)&wo16, g_wo16);
    cudaGetSymbolAddress((void**)&ticks, g_ticks);

    static bool attr_done = false;
    if (!attr_done) {
        cudaFuncSetAttribute(gemm_mma<false>, cudaFuncAttributeMaxDynamicSharedMemorySize, GEMM_SMEM);
        cudaFuncSetAttribute(gemm_mma<true>,  cudaFuncAttributeMaxDynamicSharedMemorySize, GEMM_SMEM);
        cudaFuncSetAttribute(attn_mma, cudaFuncAttributeMaxDynamicSharedMemorySize, ATTN_SMEM);
        attr_done = true;
    }

    // 1) fp32 -> fp16 converts + tick reset (single launch)
    {
        int n0 = (ML_ * KD_) / 4;
        int n1 = (NQKV_ * KD_) / 4;
        int n2 = (E_ * E_) / 4;
        int tot = n0 + n1 + n2;
        tohalf3<<<(tot + 255) / 256, 256>>>(
            (const float4*)x, (uint2*)x16, n0,
            (const float4*)W_qkv, (uint2*)wq16, n1,
            (const float4*)W_o, (uint2*)wo16, n2, ticks);
    }
    // 2) QKV projection -> fp16 (persistent, work-stealing)
    {
        int ntiles = (ML_ / BM) * (NQKV_ / BN);   // 768
        int grid = ntiles < MAX_CTAS ? ntiles : MAX_CTAS;
        gemm_mma<true><<<grid, GEMM_THREADS, GEMM_SMEM>>>(
            x16, wq16, b_qkv, nullptr, (uint32_t*)qkv16, ticks + 0,
            ML_, NQKV_, KD_, ntiles);
    }
    // 3) attention -> fp16 (band-skipping)
    attn_mma<<<dim3(L_ / QROWS, H_, B_), 256, ATTN_SMEM>>>(
        qkv16, pmask, (uint32_t*)att16);
    // 4) output projection -> fp32 (persistent, work-stealing)
    {
        int ntiles = (ML_ / BM) * (E_ / BN);      // 256
        int grid = ntiles < MAX_CTAS ? ntiles : MAX_CTAS;
        gemm_mma<false><<<grid, GEMM_THREADS, GEMM_SMEM>>>(
            att16, wo16, b_o, out, nullptr, ticks + 1,
            ML_, E_, KD_, ntiles);
    }
}

// round 10
// speedup vs baseline: 2.8363x; 1.0822x over previous
#include <cuda_runtime.h>
#include <cuda_fp16.h>
#include <cstdint>
#include <math.h>

// Problem constants
#define B_    2
#define L_    2048
#define E_    1024
#define H_    16
#define HD_   64
#define KD_   1024
#define NQKV_ 3072
#define ML_   (B_*L_)   // 4096

// ---------------- GEMM tiling (fp16 single product) ----------------
#define BM 128
#define BN 128
#define BK 64
#define ROWB 144
#define B_OFF   (128 * ROWB)
#define STAGEB  (256 * ROWB)        // 36864
#define GEMM_SMEM (2 * STAGEB)      // 73728

// ---------------- attention tiling ----------------
#define AROWB 144
#define QROWS 128
#define KROWS 192
#define S_Q  0
#define S_K  (S_Q + QROWS*AROWB)
#define S_V  (S_K + KROWS*AROWB)
#define S_OK (S_V + KROWS*AROWB)
#define ATTN_SMEM (S_OK + KROWS*4)  // 74496

#define MEGA_SMEM (ATTN_SMEM > GEMM_SMEM ? ATTN_SMEM : GEMM_SMEM)
#define MEGA_CTAS 296

// Ticket layout
#define T_G1   768                  // gemm1 tiles (32 x 24)
#define T_ATT  512                  // attention tiles (16 qb x 2 b x 16 h)
#define T_G0   256                  // gemm0 tiles (32 x 8)
#define T_TOT  (T_G1 + T_ATT + T_G0)

// ---------------- scratch ----------------
__device__ __half g_qkv16[(size_t)ML_ * NQKV_];
__device__ __half g_att16[(size_t)ML_ * E_];
__device__ __half g_x16[(size_t)ML_ * KD_];
__device__ __half g_wq16[(size_t)NQKV_ * KD_];
__device__ __half g_wo16[(size_t)E_ * E_];
// [0] tick, [1..768] g1 flags, [769..800] fa flags
__device__ unsigned g_sync[1 + 768 + 32];

// ---------------- helpers ----------------
__device__ __forceinline__ uint32_t smem_u32(const void* p) {
    uint32_t a;
    asm("{ .reg .u64 t; cvta.to.shared.u64 t, %1; cvt.u32.u64 %0, t; }" : "=r"(a) : "l"(p));
    return a;
}
#define CP16(dst, src) \
    asm volatile("cp.async.cg.shared.global [%0], [%1], 16;" :: "r"(dst), "l"(src))
#define CP_COMMIT() asm volatile("cp.async.commit_group;" ::: "memory")
#define CP_WAIT(n)  asm volatile("cp.async.wait_group %0;" :: "n"(n) : "memory")

#define LDSM_X4(r0, r1, r2, r3, a) \
    asm volatile("ldmatrix.sync.aligned.m8n8.x4.shared.b16 {%0,%1,%2,%3}, [%4];" \
                 : "=r"(r0), "=r"(r1), "=r"(r2), "=r"(r3) : "r"(a))
#define LDSM_X4_T(r0, r1, r2, r3, a) \
    asm volatile("ldmatrix.sync.aligned.m8n8.x4.trans.shared.b16 {%0,%1,%2,%3}, [%4];" \
                 : "=r"(r0), "=r"(r1), "=r"(r2), "=r"(r3) : "r"(a))

__device__ __forceinline__ void mma_f16(float c[4], const uint32_t a[4],
                                        uint32_t b0, uint32_t b1) {
    asm volatile(
        "mma.sync.aligned.m16n8k16.row.col.f32.f16.f16.f32 "
        "{%0,%1,%2,%3}, {%4,%5,%6,%7}, {%8,%9}, {%0,%1,%2,%3};"
        : "+f"(c[0]), "+f"(c[1]), "+f"(c[2]), "+f"(c[3])
        : "r"(a[0]), "r"(a[1]), "r"(a[2]), "r"(a[3]), "r"(b0), "r"(b1));
}

__device__ __forceinline__ uint32_t pk_h2(float x, float y) {
    __half2 t = __floats2half2_rn(x, y);
    return *(uint32_t*)&t;
}

// ---------------------------------------------------------------------------
// One GEMM tile: C[bm:bm+128, bn:bn+128] = A*B^T + bias
// ---------------------------------------------------------------------------
template<bool F16OUT>
__device__ __forceinline__ void gemm_tile(
    char* smem, uint32_t sbase,
    const __half* __restrict__ A, const __half* __restrict__ Bm,
    const float* __restrict__ bias, float* __restrict__ Cf,
    uint32_t* __restrict__ Ch, int bm, int bn, int K, int N)
{
    const int tid  = threadIdx.x;
    const int lane = tid & 31;
    const int wid  = tid >> 5;
    const int warp_m = wid >> 1;
    const int warp_n = wid & 1;
    const int NT = K / BK;

    const int tr = tid >> 3;
    const int lc = tid & 7;
    const __half* Abase = A + (size_t)bm * K;
    const __half* Bbase = Bm + (size_t)bn * K;
    size_t offA[4];
    uint32_t dstA[4];
#pragma unroll
    for (int i = 0; i < 4; ++i) {
        int ra = i * 32 + tr;
        offA[i] = (size_t)ra * K + lc * 8;
        dstA[i] = (uint32_t)(ra * ROWB + lc * 16);
    }

    const uint32_t aOff = (uint32_t)((warp_m * 32 + (lane & 15)) * ROWB + (lane >> 4) * 16);
    const uint32_t bOff = (uint32_t)(B_OFF +
        (warp_n * 64 + ((lane >> 4) << 3) + (lane & 7)) * ROWB + ((lane >> 3) & 1) * 16);

    float acc[2][8][4];
#pragma unroll
    for (int mt = 0; mt < 2; ++mt)
#pragma unroll
        for (int nt = 0; nt < 8; ++nt)
#pragma unroll
            for (int j = 0; j < 4; ++j) acc[mt][nt][j] = 0.0f;

    {
        uint32_t sb = sbase;
#pragma unroll
        for (int i = 0; i < 4; ++i) {
            CP16(sb + dstA[i], Abase + offA[i]);
            CP16(sb + dstA[i] + B_OFF, Bbase + offA[i]);
        }
        CP_COMMIT();
    }

    for (int kt = 0; kt < NT; ++kt) {
        CP_WAIT(0);
        __syncthreads();
        if (kt + 1 < NT) {
            uint32_t sb = sbase + ((kt + 1) & 1) * STAGEB;
            int koff = (kt + 1) * BK;
#pragma unroll
            for (int i = 0; i < 4; ++i) {
                CP16(sb + dstA[i], Abase + offA[i] + koff);
                CP16(sb + dstA[i] + B_OFF, Bbase + offA[i] + koff);
            }
            CP_COMMIT();
        }

        const uint32_t st = sbase + (kt & 1) * STAGEB;
#pragma unroll
        for (int s = 0; s < 4; ++s) {
            uint32_t af[2][4], bf[8][2];
#pragma unroll
            for (int mt = 0; mt < 2; ++mt) {
                uint32_t a = st + aOff + mt * 16 * ROWB + s * 32;
                LDSM_X4(af[mt][0], af[mt][1], af[mt][2], af[mt][3], a);
            }
#pragma unroll
            for (int p = 0; p < 4; ++p) {
                uint32_t a = st + bOff + p * 16 * ROWB + s * 32;
                LDSM_X4(bf[2*p][0], bf[2*p][1], bf[2*p+1][0], bf[2*p+1][1], a);
            }
#pragma unroll
            for (int mt = 0; mt < 2; ++mt)
#pragma unroll
                for (int nt = 0; nt < 8; ++nt)
                    mma_f16(acc[mt][nt], af[mt], bf[nt][0], bf[nt][1]);
        }
        __syncthreads();
    }

    const int r0 = bm + warp_m * 32 + (lane >> 2);
    const int c0 = bn + warp_n * 64 + (lane & 3) * 2;
#pragma unroll
    for (int mt = 0; mt < 2; ++mt) {
#pragma unroll
        for (int nt = 0; nt < 8; ++nt) {
            int col = c0 + nt * 8;
            float bx = bias[col], by = bias[col + 1];
            float vx0 = acc[mt][nt][0] + bx, vy0 = acc[mt][nt][1] + by;
            float vx1 = acc[mt][nt][2] + bx, vy1 = acc[mt][nt][3] + by;
            int ra = r0 + mt * 16, rb = ra + 8;
            if (F16OUT) {
                Ch[(size_t)ra * (N >> 1) + (col >> 1)] = pk_h2(vx0, vy0);
                Ch[(size_t)rb * (N >> 1) + (col >> 1)] = pk_h2(vx1, vy1);
            } else {
                *(float2*)(Cf + (size_t)ra * N + col) = make_float2(vx0, vy0);
                *(float2*)(Cf + (size_t)rb * N + col) = make_float2(vx1, vy1);
            }
        }
    }
}

// ---------------------------------------------------------------------------
// One band-skipping attention tile (b, h, q0..q0+127), 256 threads.
// ---------------------------------------------------------------------------
__device__ __forceinline__ void attn_tile(
    char* smem, uint32_t sb,
    const __half* __restrict__ qkv, const int* __restrict__ pmask,
    uint32_t* __restrict__ Oh, int b, int h, int q0)
{
    const int tid = threadIdx.x, lane = tid & 31, w = tid >> 5;

    for (int i = tid; i < QROWS * 8; i += 256) {
        int r = i >> 3, c = i & 7;
        size_t g = (size_t)(b * L_ + q0 + r) * NQKV_ + h * 192 + c * 8;
        *(uint4*)(smem + S_Q + r * AROWB + c * 16) = *(const uint4*)(qkv + g);
    }
    for (int i = tid; i < KROWS * 8; i += 256) {
        int r = i >> 3, c = i & 7;
        int pos = q0 - 32 + r;
        uint4 kv = make_uint4(0, 0, 0, 0), vv = make_uint4(0, 0, 0, 0);
        if (pos >= 0 && pos < L_) {
            size_t g = (size_t)(b * L_ + pos) * NQKV_ + h * 192 + c * 8;
            kv = *(const uint4*)(qkv + g + 64);
            vv = *(const uint4*)(qkv + g + 128);
        }
        *(uint4*)(smem + S_K + r * AROWB + c * 16) = kv;
        *(uint4*)(smem + S_V + r * AROWB + c * 16) = vv;
    }
    if (tid < KROWS) {
        int pos = q0 - 32 + tid;
        int ok = (pos >= 0 && pos < L_) ? (pmask[b * L_ + pos] != 0) : 0;
        ((int*)(smem + S_OK))[tid] = ok;
    }
    __syncthreads();
    const int* okk = (const int*)(smem + S_OK);

    float S[10][4];
#pragma unroll
    for (int i = 0; i < 10; ++i)
#pragma unroll
        for (int j = 0; j < 4; ++j) S[i][j] = 0.0f;

    uint32_t qf[4][4];
    {
        uint32_t aoff = (uint32_t)((w * 16 + (lane & 15)) * AROWB + (lane >> 4) * 16);
#pragma unroll
        for (int ks = 0; ks < 4; ++ks)
            LDSM_X4(qf[ks][0], qf[ks][1], qf[ks][2], qf[ks][3], sb + S_Q + aoff + ks * 32);
    }
    {
        uint32_t boff = (uint32_t)(((((lane >> 4) << 3) + (lane & 7)) * AROWB) + ((lane >> 3) & 1) * 16);
#pragma unroll
        for (int kbl = 0; kbl < 5; ++kbl) {
            uint32_t base = boff + (w + kbl) * 16 * AROWB;
#pragma unroll
            for (int ks = 0; ks < 4; ++ks) {
                uint32_t b0, b1, b2, b3;
                LDSM_X4(b0, b1, b2, b3, sb + S_K + base + ks * 32);
                mma_f16(S[2 * kbl],     qf[ks], b0, b1);
                mma_f16(S[2 * kbl + 1], qf[ks], b2, b3);
            }
        }
    }

    const int qlo = w * 16 + (lane >> 2);
    const float scale = 0.125f;
    const float NEGS = -12500.0f;
    float mlo = -3.0e38f, mhi = -3.0e38f;
#pragma unroll
    for (int nbl = 0; nbl < 10; ++nbl) {
        int kbl = nbl >> 1, grp = nbl & 1;
#pragma unroll
        for (int p = 0; p < 2; ++p) {
            int j = (w + kbl) * 16 + grp * 8 + (lane & 3) * 2 + p;
            float s0 = S[nbl][p];
            int d0 = j - qlo;
            s0 = (d0 >= 0 && d0 <= 64) ? (okk[j] ? s0 * scale : NEGS) : -3.0e38f;
            S[nbl][p] = s0;
            mlo = fmaxf(mlo, s0);
            float s1 = S[nbl][2 + p];
            int d1 = j - (qlo + 8);
            s1 = (d1 >= 0 && d1 <= 64) ? (okk[j] ? s1 * scale : NEGS) : -3.0e38f;
            S[nbl][2 + p] = s1;
            mhi = fmaxf(mhi, s1);
        }
    }
#pragma unroll
    for (int o = 1; o <= 2; o <<= 1) {
        mlo = fmaxf(mlo, __shfl_xor_sync(0xffffffffu, mlo, o));
        mhi = fmaxf(mhi, __shfl_xor_sync(0xffffffffu, mhi, o));
    }
    float slo = 0.f, shi = 0.f;
#pragma unroll
    for (int nbl = 0; nbl < 10; ++nbl) {
#pragma unroll
        for (int p = 0; p < 2; ++p) {
            float e0 = __expf(S[nbl][p] - mlo);     S[nbl][p] = e0;     slo += e0;
            float e1 = __expf(S[nbl][2 + p] - mhi); S[nbl][2 + p] = e1; shi += e1;
        }
    }
#pragma unroll
    for (int o = 1; o <= 2; o <<= 1) {
        slo += __shfl_xor_sync(0xffffffffu, slo, o);
        shi += __shfl_xor_sync(0xffffffffu, shi, o);
    }
    const float invlo = 1.0f / slo;
    const float invhi = 1.0f / shi;

    uint32_t pf[5][4];
#pragma unroll
    for (int kbl = 0; kbl < 5; ++kbl) {
        pf[kbl][0] = pk_h2(S[2 * kbl][0] * invlo,     S[2 * kbl][1] * invlo);
        pf[kbl][1] = pk_h2(S[2 * kbl][2] * invhi,     S[2 * kbl][3] * invhi);
        pf[kbl][2] = pk_h2(S[2 * kbl + 1][0] * invlo, S[2 * kbl + 1][1] * invlo);
        pf[kbl][3] = pk_h2(S[2 * kbl + 1][2] * invhi, S[2 * kbl + 1][3] * invhi);
    }

    float O[8][4];
#pragma unroll
    for (int i = 0; i < 8; ++i)
#pragma unroll
        for (int j = 0; j < 4; ++j) O[i][j] = 0.0f;

    {
        uint32_t voff = (uint32_t)((lane & 15) * AROWB + (lane >> 4) * 16);
#pragma unroll
        for (int kbl = 0; kbl < 5; ++kbl) {
            uint32_t base = voff + (w + kbl) * 16 * AROWB;
#pragma unroll
            for (int db = 0; db < 4; ++db) {
                uint32_t v0, v1, v2, v3;
                LDSM_X4_T(v0, v1, v2, v3, sb + S_V + base + db * 32);
                mma_f16(O[2 * db],     pf[kbl], v0, v1);
                mma_f16(O[2 * db + 1], pf[kbl], v2, v3);
            }
        }
    }

    const size_t rowlo = (size_t)(b * L_ + q0 + qlo);
    const size_t rowhi = rowlo + 8;
#pragma unroll
    for (int nb = 0; nb < 8; ++nb) {
        int col = h * 64 + nb * 8 + (lane & 3) * 2;
        Oh[rowlo * (E_ / 2) + (col >> 1)] = pk_h2(O[nb][0], O[nb][1]);
        Oh[rowhi * (E_ / 2) + (col >> 1)] = pk_h2(O[nb][2], O[nb][3]);
    }
}

// ---------------------------------------------------------------------------
// Fused pipeline kernel: gemm1 -> attn -> gemm0, flag-gated work stealing.
// ---------------------------------------------------------------------------
__global__ __launch_bounds__(256, 2) void mega(
    const __half* __restrict__ x16, const __half* __restrict__ wq16,
    const float* __restrict__ b_qkv, __half* __restrict__ qkv16,
    const int* __restrict__ pmask, __half* __restrict__ att16,
    const __half* __restrict__ wo16, const float* __restrict__ b_o,
    float* __restrict__ out)
{
    extern __shared__ char smem[];
    __shared__ unsigned s_t;
    const uint32_t sbase = smem_u32(smem);
    unsigned* tick = &g_sync[0];
    unsigned* g1   = &g_sync[1];
    unsigned* fa   = &g_sync[769];

    for (;;) {
        __syncthreads();
        if (threadIdx.x == 0) s_t = atomicAdd(tick, 1u);
        __syncthreads();
        const unsigned t = s_t;
        if (t >= (unsigned)T_TOT) break;

        if (t < (unsigned)T_G1) {
            // QKV projection tile; batches interleaved so early rows finish first
            int i = (int)t / 24, bn_i = (int)t % 24;
            int bm_i = ((i & 1) << 4) + (i >> 1);
            gemm_tile<true>(smem, sbase, x16, wq16, b_qkv, nullptr,
                            (uint32_t*)qkv16, bm_i * 128, bn_i * 128, KD_, NQKV_);
            __threadfence();
            __syncthreads();
            if (threadIdx.x == 0) atomicExch(&g1[bm_i * 24 + bn_i], 1u);
        } else if (t < (unsigned)(T_G1 + T_ATT)) {
            // attention tile (qb-major so row blocks complete early)
            unsigned a = t - T_G1;
            int qb = (int)(a >> 5), b = (int)((a >> 4) & 1), h = (int)(a & 15);
            if (threadIdx.x == 0) {
                int ct0 = (3 * h) >> 1;
                for (int rb = qb - 1; rb <= qb + 1; ++rb) {
                    if (rb < 0 || rb > 15) continue;
                    int base = (b * 16 + rb) * 24 + ct0;
                    while (((volatile unsigned*)g1)[base] == 0u) __nanosleep(64);
                    while (((volatile unsigned*)g1)[base + 1] == 0u) __nanosleep(64);
                }
                __threadfence();
            }
            __syncthreads();
            attn_tile(smem, sbase, qkv16, pmask, (uint32_t*)att16, b, h, qb * 128);
            __threadfence();
            __syncthreads();
            if (threadIdx.x == 0) atomicAdd(&fa[b * 16 + qb], 1u);
        } else {
            // output projection tile
            unsigned g = t - (T_G1 + T_ATT);
            int j = (int)(g >> 3), bn_i = (int)(g & 7);
            int bm_i = ((j & 1) << 4) + (j >> 1);
            if (threadIdx.x == 0) {
                while (((volatile unsigned*)fa)[bm_i] < 16u) __nanosleep(64);
                __threadfence();
            }
            __syncthreads();
            gemm_tile<false>(smem, sbase, att16, wo16, b_o, out,
                             nullptr, bm_i * 128, bn_i * 128, KD_, E_);
        }
    }
}

// ---------------------------------------------------------------------------
// fp32 -> fp16 converts (one launch) + sync-state reset
// ---------------------------------------------------------------------------
__global__ __launch_bounds__(256) void tohalf3(
    const float4* __restrict__ s0, uint2* __restrict__ d0, int n0,
    const float4* __restrict__ s1, uint2* __restrict__ d1, int n1,
    const float4* __restrict__ s2, uint2* __restrict__ d2, int n2,
    unsigned* __restrict__ sync)
{
    int i = blockIdx.x * blockDim.x + threadIdx.x;
    if (i < 1 + 768 + 32) sync[i] = 0;
    const float4* s; uint2* d;
    if (i < n0)           { s = s0 + i; d = d0 + i; }
    else if (i < n0 + n1) { s = s1 + (i - n0); d = d1 + (i - n0); }
    else if (i < n0 + n1 + n2) { s = s2 + (i - n0 - n1); d = d2 + (i - n0 - n1); }
    else return;
    float4 v = *s;
    *d = make_uint2(pk_h2(v.x, v.y), pk_h2(v.z, v.w));
}

// ---------------------------------------------------------------------------
// kernel_launch
// ---------------------------------------------------------------------------
extern "C" void kernel_launch(void* const* d_in, const int* in_sizes, int n_in,
                              void* d_out, int out_size)
{
    const float* x      = (const float*)d_in[0];
    const int*   pmask  = (const int*)d_in[1];
    const float* W_qkv  = (const float*)d_in[2];
    const float* b_qkv  = (const float*)d_in[3];
    const float* W_o    = (const float*)d_in[4];
    const float* b_o    = (const float*)d_in[5];
    float* out = (float*)d_out;

    __half *qkv16, *att16, *x16, *wq16, *wo16;
    unsigned* syncp;
    cudaGetSymbolAddress((void**)&qkv16, g_qkv16);
    cudaGetSymbolAddress((void**)&att16, g_att16);
    cudaGetSymbolAddress((void**)&x16, g_x16);
    cudaGetSymbolAddress((void**)&wq16, g_wq16);
    cudaGetSymbolAddress((void**)&wo16, g_wo16);
    cudaGetSymbolAddress((void**)&syncp, g_sync);

    static bool attr_done = false;
    if (!attr_done) {
        cudaFuncSetAttribute(mega, cudaFuncAttributeMaxDynamicSharedMemorySize, MEGA_SMEM);
        attr_done = true;
    }

    // 1) fp32 -> fp16 converts + sync reset
    {
        int n0 = (ML_ * KD_) / 4;
        int n1 = (NQKV_ * KD_) / 4;
        int n2 = (E_ * E_) / 4;
        int tot = n0 + n1 + n2;
        tohalf3<<<(tot + 255) / 256, 256>>>(
            (const float4*)x, (uint2*)x16, n0,
            (const float4*)W_qkv, (uint2*)wq16, n1,
            (const float4*)W_o, (uint2*)wo16, n2, syncp);
    }
    // 2) fused gemm1 -> attn -> gemm0 pipeline
    mega<<<MEGA_CTAS, 256, MEGA_SMEM>>>(
        x16, wq16, b_qkv, qkv16, pmask, att16, wo16, b_o, out);
}